// round 6
// baseline (speedup 1.0000x reference)
#include <cuda_runtime.h>
#include <cuda_fp16.h>
#include <cstdint>
#include <cstddef>

// Problem constants
#define HH 2048
#define BB 256
#define TT 200
#define VV 512
#define LL 2

#define LO_SCALE 4096.0f
#define LO_INV   (1.0f / 4096.0f)

// ---------------------------------------------------------------------------
// Scratch (static __device__ — no allocations allowed)
// All GEMM operands stored as fp16 (hi, lo*4096) pairs in separate arrays.
// ---------------------------------------------------------------------------
__device__ __align__(128) __half g_Wih0h[HH * HH];
__device__ __align__(128) __half g_Wih0l[HH * HH];
__device__ __align__(128) __half g_Whh0h[HH * HH];
__device__ __align__(128) __half g_Whh0l[HH * HH];
__device__ __align__(128) __half g_Wih1h[HH * HH];
__device__ __align__(128) __half g_Wih1l[HH * HH];
__device__ __align__(128) __half g_Whh1h[HH * HH];
__device__ __align__(128) __half g_Whh1l[HH * HH];
__device__ __align__(128) __half g_embh[VV * HH];
__device__ __align__(128) __half g_embl[VV * HH];
__device__ __align__(128) __half g_fcwh[VV * HH];
__device__ __align__(128) __half g_fcwl[VV * HH];
__device__ __align__(128) float  g_Eprime[VV * HH];
__device__ __align__(128) __half g_h0h[2][BB * HH];
__device__ __align__(128) __half g_h0l[2][BB * HH];
__device__ __align__(128) __half g_h1h[2][BB * HH];
__device__ __align__(128) __half g_h1l[2][BB * HH];
__device__ __align__(128) __half g_outsh[(size_t)TT * BB * HH];
__device__ __align__(128) __half g_outsl[(size_t)TT * BB * HH];

// ---------------------------------------------------------------------------
// Helpers
// ---------------------------------------------------------------------------
__device__ __forceinline__ void f16_split(float x, __half& hi, __half& lo) {
    __half h = __float2half_rn(x);
    float r = x - __half2float(h);             // exact in fp32
    hi = h;
    lo = __float2half_rn(r * LO_SCALE);
}

// tanh immune to --use_fast_math's tanh.approx (too inaccurate).
__device__ __forceinline__ float my_tanh(float x) {
    float e = __expf(2.0f * x);
    return 1.0f - 2.0f / (e + 1.0f);
}

__device__ __forceinline__ void cp16(uint32_t smem_addr, const void* src) {
    asm volatile("cp.async.cg.shared.global [%0], [%1], 16;\n"
                 :: "r"(smem_addr), "l"(src));
}

__device__ __forceinline__ void ldsm4(uint32_t* r, uint32_t addr) {
    asm volatile("ldmatrix.sync.aligned.m8n8.x4.shared.b16 {%0,%1,%2,%3}, [%4];\n"
                 : "=r"(r[0]), "=r"(r[1]), "=r"(r[2]), "=r"(r[3])
                 : "r"(addr));
}

__device__ __forceinline__ void mma16(float* c, const uint32_t* a, const uint32_t* b) {
    asm volatile(
        "mma.sync.aligned.m16n8k16.row.col.f32.f16.f16.f32 "
        "{%0,%1,%2,%3}, {%4,%5,%6,%7}, {%8,%9}, {%0,%1,%2,%3};\n"
        : "+f"(c[0]), "+f"(c[1]), "+f"(c[2]), "+f"(c[3])
        : "r"(a[0]), "r"(a[1]), "r"(a[2]), "r"(a[3]),
          "r"(b[0]), "r"(b[1]));
}

__device__ __forceinline__ uint32_t smem_u32(const void* p) {
    return (uint32_t)__cvta_generic_to_shared(p);
}

// ---------------------------------------------------------------------------
// Prep: split all weights + initial hidden state into fp16 hi/lo
// ---------------------------------------------------------------------------
__global__ void prep_kernel(const float* __restrict__ h0,
                            const float* __restrict__ emb,
                            const float* __restrict__ Wih,
                            const float* __restrict__ Whh,
                            const float* __restrict__ fcw) {
    int idx = blockIdx.x * blockDim.x + threadIdx.x;
    int stride = gridDim.x * blockDim.x;
    for (int i = idx; i < HH * HH; i += stride) {
        f16_split(Wih[i],           g_Wih0h[i], g_Wih0l[i]);
        f16_split(Wih[HH * HH + i], g_Wih1h[i], g_Wih1l[i]);
        f16_split(Whh[i],           g_Whh0h[i], g_Whh0l[i]);
        f16_split(Whh[HH * HH + i], g_Whh1h[i], g_Whh1l[i]);
    }
    for (int i = idx; i < VV * HH; i += stride) {
        f16_split(emb[i], g_embh[i], g_embl[i]);
        f16_split(fcw[i], g_fcwh[i], g_fcwl[i]);
    }
    for (int i = idx; i < BB * HH; i += stride) {
        f16_split(h0[i],           g_h0h[0][i], g_h0l[0][i]);
        f16_split(h0[BB * HH + i], g_h1h[0][i], g_h1l[0][i]);
    }
}

// ---------------------------------------------------------------------------
// Pair kernel: one launch runs step1(c-1) [z=0] and step0(c) [z=1] which are
// mutually independent (both depend only on launch c-1's outputs).
//   step0(t): h0' = tanh(h0[p] @ Whh0^T + Eprime[tok])  -> h0[p^1],  K=2048
//   step1(t): h1' = tanh(h0[p^1] @ Wih1^T + h1[p] @ Whh1^T + b1)
//             -> h1[p^1], outs[t],                                   K=4096
// CTA tile: BM=64, BN=32, BK=32. 128 threads = 4 warps (2M x 2N),
// warp tile 32x16. 3-stage cp.async pipeline. occ target 4 CTAs/SM.
// ---------------------------------------------------------------------------
#define ROWB 80      // bytes per smem row (40 halves)

__global__ __launch_bounds__(128, 4) void step_pair_kernel(
    const int* __restrict__ tokens,
    const float* __restrict__ b_ih,
    const float* __restrict__ b_hh,
    int c)
{
    __shared__ __align__(16) __half Ash[3][64][40];
    __shared__ __align__(16) __half Asl[3][64][40];
    __shared__ __align__(16) __half Bsh[3][32][40];
    __shared__ __align__(16) __half Bsl[3][32][40];

    const int part = blockIdx.z;   // 0 = step1(c-1), 1 = step0(c)
    int t, KT;
    const __half *A0h, *A0l, *B0h, *B0l;
    const __half *A1h = nullptr, *A1l = nullptr, *B1h = nullptr, *B1l = nullptr;
    if (part == 0) {
        if (c == 0) return;
        t = c - 1; KT = 128;
        const int p = t & 1;
        A0h = g_h0h[p ^ 1]; A0l = g_h0l[p ^ 1]; B0h = g_Wih1h; B0l = g_Wih1l;
        A1h = g_h1h[p];     A1l = g_h1l[p];     B1h = g_Whh1h; B1l = g_Whh1l;
    } else {
        if (c >= TT) return;
        t = c; KT = 64;
        const int p = t & 1;
        A0h = g_h0h[p]; A0l = g_h0l[p]; B0h = g_Whh0h; B0l = g_Whh0l;
    }
    const int p = t & 1;

    const int m0 = blockIdx.y * 64;
    const int n0 = blockIdx.x * 32;
    const int tid = threadIdx.x;
    const int lane = tid & 31;
    const int warp = tid >> 5;
    const int wm = warp & 1;    // 2 warps over M (32 rows each)
    const int wn = warp >> 1;   // 2 warps over N (16 cols each)

    const uint32_t smAh = smem_u32(&Ash[0][0][0]);
    const uint32_t smAl = smem_u32(&Asl[0][0][0]);
    const uint32_t smBh = smem_u32(&Bsh[0][0][0]);
    const uint32_t smBl = smem_u32(&Bsl[0][0][0]);
    const uint32_t ASTG = 64 * ROWB;   // 5120 B per A stage
    const uint32_t BSTG = 32 * ROWB;   // 2560 B per B stage

    // ldmatrix per-lane addresses (same fragment layout as validated R4 kernel)
    const int rowA = (lane & 7) + ((lane >> 3) & 1) * 8;
    const int colA = (lane >> 4) * 8;
    const int rowB = (lane & 7) + (lane >> 4) * 8;
    const int colB = ((lane >> 3) & 1) * 8;
    const uint32_t aOffH = smAh + (uint32_t)((wm * 32 + rowA) * ROWB + colA * 2);
    const uint32_t aOffL = smAl + (uint32_t)((wm * 32 + rowA) * ROWB + colA * 2);
    const uint32_t bOffH = smBh + (uint32_t)((wn * 16 + rowB) * ROWB + colB * 2);
    const uint32_t bOffL = smBl + (uint32_t)((wn * 16 + rowB) * ROWB + colB * 2);

    float accH[2][2][4];
    float accX[2][2][4];
#pragma unroll
    for (int i = 0; i < 2; i++)
#pragma unroll
        for (int j = 0; j < 2; j++)
#pragma unroll
            for (int k = 0; k < 4; k++) { accH[i][j][k] = 0.0f; accX[i][j][k] = 0.0f; }

    // Stage loader: 128 threads. A: 256 16B-chunks (2/thread/array), B: 128 (1/thread/array)
    auto load_tile = [&](int kt, int s) {
        const __half *sAh = A0h, *sAl = A0l, *sBh = B0h, *sBl = B0l;
        int kk = kt * 32;
        if (part == 0 && kt >= 64) {
            sAh = A1h; sAl = A1l; sBh = B1h; sBl = B1l; kk = (kt - 64) * 32;
        }
#pragma unroll
        for (int j = 0; j < 2; j++) {
            const int idx = tid + j * 128;
            const int row = idx >> 2;
            const int c16 = (idx & 3) * 8;   // halves
            const size_t g = (size_t)(m0 + row) * HH + kk + c16;
            const uint32_t so = (uint32_t)(s * (int)ASTG + row * ROWB + c16 * 2);
            cp16(smAh + so, sAh + g);
            cp16(smAl + so, sAl + g);
        }
        {
            const int row = tid >> 2;
            const int c16 = (tid & 3) * 8;
            const size_t g = (size_t)(n0 + row) * HH + kk + c16;
            const uint32_t so = (uint32_t)(s * (int)BSTG + row * ROWB + c16 * 2);
            cp16(smBh + so, sBh + g);
            cp16(smBl + so, sBl + g);
        }
        asm volatile("cp.async.commit_group;\n" ::: "memory");
    };

    load_tile(0, 0);
    load_tile(1, 1);

    for (int kt = 0; kt < KT; kt++) {
        const int s = kt % 3;
        if (kt < KT - 1) {
            asm volatile("cp.async.wait_group 1;\n" ::: "memory");
        } else {
            asm volatile("cp.async.wait_group 0;\n" ::: "memory");
        }
        __syncthreads();
        if (kt + 2 < KT) load_tile(kt + 2, (kt + 2) % 3);

        const uint32_t sbA = (uint32_t)(s * (int)ASTG);
        const uint32_t sbB = (uint32_t)(s * (int)BSTG);
#pragma unroll
        for (int ks = 0; ks < 2; ks++) {
            uint32_t ah[2][4], al[2][4], bh[4], bl[4];
            const uint32_t ko = (uint32_t)(ks * 32);   // 16 halves = 32 B
#pragma unroll
            for (int mt = 0; mt < 2; mt++) {
                ldsm4(ah[mt], aOffH + sbA + (uint32_t)(mt * 16 * ROWB) + ko);
                ldsm4(al[mt], aOffL + sbA + (uint32_t)(mt * 16 * ROWB) + ko);
            }
            ldsm4(bh, bOffH + sbB + ko);
            ldsm4(bl, bOffL + sbB + ko);
#pragma unroll
            for (int mt = 0; mt < 2; mt++)
#pragma unroll
                for (int nt = 0; nt < 2; nt++) {
                    mma16(accH[mt][nt], ah[mt], bh + nt * 2);
                    mma16(accX[mt][nt], al[mt], bh + nt * 2);
                    mma16(accX[mt][nt], ah[mt], bl + nt * 2);
                }
        }
    }

    // Epilogue
#pragma unroll
    for (int mt = 0; mt < 2; mt++) {
#pragma unroll
        for (int hi = 0; hi < 2; hi++) {
            const int r = m0 + wm * 32 + mt * 16 + (lane >> 2) + hi * 8;
            int tok = 0;
            if (part == 1) tok = tokens[r * TT + t];
#pragma unroll
            for (int nt = 0; nt < 2; nt++) {
#pragma unroll
                for (int lo = 0; lo < 2; lo++) {
                    const int cc = n0 + wn * 16 + nt * 8 + (lane & 3) * 2 + lo;
                    float v = accH[mt][nt][hi * 2 + lo] + accX[mt][nt][hi * 2 + lo] * LO_INV;
                    const size_t idx = (size_t)r * HH + cc;
                    if (part == 1) {
                        v += g_Eprime[(size_t)tok * HH + cc];
                        v = my_tanh(v);
                        f16_split(v, g_h0h[p ^ 1][idx], g_h0l[p ^ 1][idx]);
                    } else {
                        v += b_ih[HH + cc] + b_hh[HH + cc];
                        v = my_tanh(v);
                        __half vh, vl;
                        f16_split(v, vh, vl);
                        g_h1h[p ^ 1][idx] = vh;
                        g_h1l[p ^ 1][idx] = vl;
                        const size_t oidx = (size_t)t * BB * HH + idx;
                        g_outsh[oidx] = vh;
                        g_outsl[oidx] = vl;
                    }
                }
            }
        }
    }
}

// ---------------------------------------------------------------------------
// Legacy gemm kernel for EPRIME and LOGITS (off critical path; proven in R4).
// BM=BN=64, BK=32, 256 threads (8 warps: 2M x 4N), 2-stage.
// ---------------------------------------------------------------------------
#define MODE_EPRIME 0
#define MODE_LOGITS 3
#define STAGEB 5120

template <int MODE>
__global__ __launch_bounds__(256) void gemm_kernel(
    const float* __restrict__ b_ih,
    const float* __restrict__ b_hh,
    const float* __restrict__ fc_b,
    float* __restrict__ d_out)
{
    __shared__ __align__(16) __half Ash[2][64][40];
    __shared__ __align__(16) __half Asl[2][64][40];
    __shared__ __align__(16) __half Bsh[2][64][40];
    __shared__ __align__(16) __half Bsl[2][64][40];

    const __half *A0h, *A0l, *B0h, *B0l;
    int KT;
    if (MODE == MODE_EPRIME) {
        A0h = g_embh; A0l = g_embl; B0h = g_Wih0h; B0l = g_Wih0l; KT = 64;
    } else {
        A0h = g_outsh; A0l = g_outsl; B0h = g_fcwh; B0l = g_fcwl; KT = 64;
    }

    int m0, n0;
    if (MODE == MODE_LOGITS) { m0 = blockIdx.y * 64; n0 = blockIdx.x * 64; }
    else                     { m0 = blockIdx.x * 64; n0 = blockIdx.y * 64; }

    const int tid = threadIdx.x;
    const int lane = tid & 31;
    const int warp = tid >> 5;
    const int wm = warp & 1;
    const int wn = warp >> 1;

    const uint32_t smAh = smem_u32(&Ash[0][0][0]);
    const uint32_t smAl = smem_u32(&Asl[0][0][0]);
    const uint32_t smBh = smem_u32(&Bsh[0][0][0]);
    const uint32_t smBl = smem_u32(&Bsl[0][0][0]);

    const int rowA = (lane & 7) + ((lane >> 3) & 1) * 8;
    const int colA = (lane >> 4) * 8;
    const int rowB = (lane & 7) + (lane >> 4) * 8;
    const int colB = ((lane >> 3) & 1) * 8;
    const uint32_t aOffH = smAh + (uint32_t)((wm * 32 + rowA) * ROWB + colA * 2);
    const uint32_t aOffL = smAl + (uint32_t)((wm * 32 + rowA) * ROWB + colA * 2);
    const uint32_t bOffH = smBh + (uint32_t)((wn * 16 + rowB) * ROWB + colB * 2);
    const uint32_t bOffL = smBl + (uint32_t)((wn * 16 + rowB) * ROWB + colB * 2);

    float accH[2][2][4];
    float accX[2][2][4];
#pragma unroll
    for (int i = 0; i < 2; i++)
#pragma unroll
        for (int j = 0; j < 2; j++)
#pragma unroll
            for (int k = 0; k < 4; k++) { accH[i][j][k] = 0.0f; accX[i][j][k] = 0.0f; }

    const int lrow = tid >> 2;
    const int lc8 = (tid & 3) * 8;
    auto load_tile = [&](int kt, int s) {
        int kk = kt * 32;
        const size_t gA = (size_t)(m0 + lrow) * HH + kk + lc8;
        const size_t gB = (size_t)(n0 + lrow) * HH + kk + lc8;
        const uint32_t so = (uint32_t)(s * STAGEB + lrow * ROWB + lc8 * 2);
        cp16(smAh + so, A0h + gA);
        cp16(smAl + so, A0l + gA);
        cp16(smBh + so, B0h + gB);
        cp16(smBl + so, B0l + gB);
        asm volatile("cp.async.commit_group;\n" ::: "memory");
    };

    load_tile(0, 0);

    for (int kt = 0; kt < KT; kt++) {
        const int s = kt & 1;
        asm volatile("cp.async.wait_group 0;\n" ::: "memory");
        __syncthreads();
        if (kt + 1 < KT) load_tile(kt + 1, s ^ 1);

        const uint32_t sb = (uint32_t)(s * STAGEB);
#pragma unroll
        for (int ks = 0; ks < 2; ks++) {
            uint32_t ah[2][4], al[2][4], bh[4], bl[4];
            const uint32_t ko = (uint32_t)(ks * 32);
#pragma unroll
            for (int mt = 0; mt < 2; mt++) {
                ldsm4(ah[mt], aOffH + sb + (uint32_t)(mt * 16 * ROWB) + ko);
                ldsm4(al[mt], aOffL + sb + (uint32_t)(mt * 16 * ROWB) + ko);
            }
            ldsm4(bh, bOffH + sb + ko);
            ldsm4(bl, bOffL + sb + ko);
#pragma unroll
            for (int mt = 0; mt < 2; mt++)
#pragma unroll
                for (int nt = 0; nt < 2; nt++) {
                    mma16(accH[mt][nt], ah[mt], bh + nt * 2);
                    mma16(accX[mt][nt], al[mt], bh + nt * 2);
                    mma16(accX[mt][nt], ah[mt], bl + nt * 2);
                }
        }
    }

#pragma unroll
    for (int mt = 0; mt < 2; mt++) {
#pragma unroll
        for (int hi = 0; hi < 2; hi++) {
            const int r = m0 + wm * 32 + mt * 16 + (lane >> 2) + hi * 8;
#pragma unroll
            for (int nt = 0; nt < 2; nt++) {
#pragma unroll
                for (int lo = 0; lo < 2; lo++) {
                    const int cc = n0 + wn * 16 + nt * 8 + (lane & 3) * 2 + lo;
                    float v = accH[mt][nt][hi * 2 + lo] + accX[mt][nt][hi * 2 + lo] * LO_INV;
                    if (MODE == MODE_EPRIME) {
                        v += b_ih[cc] + b_hh[cc];
                        g_Eprime[(size_t)r * HH + cc] = v;
                    } else {
                        v += fc_b[cc];
                        d_out[(size_t)r * VV + cc] = v;
                    }
                }
            }
        }
    }
}

// ---------------------------------------------------------------------------
// h_final (last step writes parity 0 buffers)
// ---------------------------------------------------------------------------
__global__ void final_copy_kernel(float* __restrict__ d_out) {
    int i = blockIdx.x * blockDim.x + threadIdx.x;
    if (i < BB * HH) {
        d_out[(size_t)TT * BB * VV + i] =
            __half2float(g_h0h[0][i]) + __half2float(g_h0l[0][i]) * LO_INV;
        d_out[(size_t)TT * BB * VV + BB * HH + i] =
            __half2float(g_h1h[0][i]) + __half2float(g_h1l[0][i]) * LO_INV;
    }
}

// ---------------------------------------------------------------------------
// Launch
// ---------------------------------------------------------------------------
extern "C" void kernel_launch(void* const* d_in, const int* in_sizes, int n_in,
                              void* d_out, int out_size) {
    const int*   tokens = (const int*)d_in[0];
    const float* h0     = (const float*)d_in[1];
    const float* emb    = (const float*)d_in[2];
    const float* Wih    = (const float*)d_in[3];
    const float* Whh    = (const float*)d_in[4];
    const float* bih    = (const float*)d_in[5];
    const float* bhh    = (const float*)d_in[6];
    const float* fcw    = (const float*)d_in[7];
    const float* fcb    = (const float*)d_in[8];
    float* out = (float*)d_out;

    // 1) Split weights + initial state into fp16 hi/lo
    prep_kernel<<<1024, 256>>>(h0, emb, Wih, Whh, fcw);

    // 2) E'' = emb @ W_ih0^T + b_ih0 + b_hh0
    gemm_kernel<MODE_EPRIME><<<dim3(VV / 64, HH / 64), 256>>>(bih, bhh, fcb, out);

    // 3) Recurrence: 201 pair launches; launch c runs step1(c-1) || step0(c)
    for (int c = 0; c <= TT; c++) {
        step_pair_kernel<<<dim3(HH / 32, BB / 64, 2), 128>>>(tokens, bih, bhh, c);
    }

    // 4) Logits: [T*B, H] @ [V, H]^T + fc_b   (n-tile fastest for A reuse)
    gemm_kernel<MODE_LOGITS><<<dim3(VV / 64, (TT * BB) / 64), 256>>>(bih, bhh, fcb, out);

    // 5) h_final
    if (out_size >= TT * BB * VV + LL * BB * HH)
        final_copy_kernel<<<(BB * HH + 255) / 256, 256>>>(out);
}

// round 12
// speedup vs baseline: 1.3696x; 1.3696x over previous
#include <cuda_runtime.h>
#include <cuda_fp16.h>
#include <cstdint>
#include <cstddef>

// Problem constants
#define HH 2048
#define BB 256
#define TT 200
#define VV 512
#define LL 2

// ---------------------------------------------------------------------------
// Scratch (static __device__ — no allocations allowed)
// Operands stored as fp16 (hi, lo) pairs, lo UNSCALED (subnormals OK).
// ---------------------------------------------------------------------------
__device__ __align__(128) __half g_Wih0h[HH * HH];
__device__ __align__(128) __half g_Wih0l[HH * HH];
__device__ __align__(128) __half g_Whh0h[HH * HH];
__device__ __align__(128) __half g_Whh0l[HH * HH];
__device__ __align__(128) __half g_Wih1h[HH * HH];
__device__ __align__(128) __half g_Wih1l[HH * HH];
__device__ __align__(128) __half g_Whh1h[HH * HH];
__device__ __align__(128) __half g_Whh1l[HH * HH];
__device__ __align__(128) __half g_embh[VV * HH];
__device__ __align__(128) __half g_embl[VV * HH];
__device__ __align__(128) __half g_fcwh[VV * HH];
__device__ __align__(128) __half g_fcwl[VV * HH];
__device__ __align__(128) float  g_Eprime[VV * HH];
__device__ __align__(128) __half g_h0h[2][BB * HH];
__device__ __align__(128) __half g_h0l[2][BB * HH];
__device__ __align__(128) __half g_h1h[2][BB * HH];
__device__ __align__(128) __half g_h1l[2][BB * HH];
__device__ __align__(128) __half g_outsh[(size_t)TT * BB * HH];
__device__ __align__(128) __half g_outsl[(size_t)TT * BB * HH];

// Split-K partial accumulators (fp32); reduced by a separate finisher kernel.
#define KS1 8
#define KS0 4
__device__ __align__(128) float g_part1[KS1][BB * HH];
__device__ __align__(128) float g_part0[KS0][BB * HH];

// ---------------------------------------------------------------------------
// Helpers
// ---------------------------------------------------------------------------
__device__ __forceinline__ void f16_split(float x, __half& hi, __half& lo) {
    __half h = __float2half_rn(x);
    hi = h;
    lo = __float2half_rn(x - __half2float(h));   // unscaled residual
}

// tanh immune to --use_fast_math's tanh.approx (too inaccurate).
__device__ __forceinline__ float my_tanh(float x) {
    float e = __expf(2.0f * x);
    return 1.0f - 2.0f / (e + 1.0f);
}

__device__ __forceinline__ void cp16(uint32_t smem_addr, const void* src) {
    asm volatile("cp.async.cg.shared.global [%0], [%1], 16;\n"
                 :: "r"(smem_addr), "l"(src));
}

__device__ __forceinline__ void ldsm4(uint32_t* r, uint32_t addr) {
    asm volatile("ldmatrix.sync.aligned.m8n8.x4.shared.b16 {%0,%1,%2,%3}, [%4];\n"
                 : "=r"(r[0]), "=r"(r[1]), "=r"(r[2]), "=r"(r[3])
                 : "r"(addr));
}

__device__ __forceinline__ void mma16(float* c, const uint32_t* a, const uint32_t* b) {
    asm volatile(
        "mma.sync.aligned.m16n8k16.row.col.f32.f16.f16.f32 "
        "{%0,%1,%2,%3}, {%4,%5,%6,%7}, {%8,%9}, {%0,%1,%2,%3};\n"
        : "+f"(c[0]), "+f"(c[1]), "+f"(c[2]), "+f"(c[3])
        : "r"(a[0]), "r"(a[1]), "r"(a[2]), "r"(a[3]),
          "r"(b[0]), "r"(b[1]));
}

__device__ __forceinline__ uint32_t smem_u32(const void* p) {
    return (uint32_t)__cvta_generic_to_shared(p);
}

// ---------------------------------------------------------------------------
// Prep: split all weights + initial hidden state into fp16 hi/lo
// ---------------------------------------------------------------------------
__global__ void prep_kernel(const float* __restrict__ h0,
                            const float* __restrict__ emb,
                            const float* __restrict__ Wih,
                            const float* __restrict__ Whh,
                            const float* __restrict__ fcw) {
    int idx = blockIdx.x * blockDim.x + threadIdx.x;
    int stride = gridDim.x * blockDim.x;
    for (int i = idx; i < HH * HH; i += stride) {
        f16_split(Wih[i],           g_Wih0h[i], g_Wih0l[i]);
        f16_split(Wih[HH * HH + i], g_Wih1h[i], g_Wih1l[i]);
        f16_split(Whh[i],           g_Whh0h[i], g_Whh0l[i]);
        f16_split(Whh[HH * HH + i], g_Whh1h[i], g_Whh1l[i]);
    }
    for (int i = idx; i < VV * HH; i += stride) {
        f16_split(emb[i], g_embh[i], g_embl[i]);
        f16_split(fcw[i], g_fcwh[i], g_fcwl[i]);
    }
    for (int i = idx; i < BB * HH; i += stride) {
        f16_split(h0[i],           g_h0h[0][i], g_h0l[0][i]);
        f16_split(h0[BB * HH + i], g_h1h[0][i], g_h1l[0][i]);
    }
}

// ---------------------------------------------------------------------------
// Pair GEMM with split-K (partials only; reduction in finisher_kernel).
// Launch c computes:
//   lay=1 (z 0..7):  step1(c-1) partials: h0'@Wih1^T + h1@Whh1^T, K=4096
//   lay=0 (z 8..11): step0(c)   partials: h0 @Whh0^T,             K=2048
// CTA tile BM=128, BN=128, BK=16, 2-stage STATIC smem (40 KB), 256 threads
// = 8 warps (4M x 2N), warp region 32x64, single fp32 acc, 3 mma passes.
// Smem row (80 B, 16-aligned, conflict-free): [16 hi halves|16 lo halves|pad].
// Each k-chunk = 32 stages of BK=16.
// ---------------------------------------------------------------------------
#define ROWB_P 80                 // bytes per smem row
#define ARR_P  (128 * ROWB_P)     // 10240 B per operand (A or B)
#define STAGE_P (2 * ARR_P)       // 20480 B per stage
#define OFF_A 0
#define OFF_B ARR_P
#define SPC 32                    // stages per k-chunk

__global__ __launch_bounds__(256, 2) void pair_gemm_kernel(int c)
{
    __shared__ __align__(16) char sm[2 * STAGE_P];   // 40960 B, static

    const int tid = threadIdx.x;
    const int lane = tid & 31;
    const int warp = tid >> 5;
    const int wm = warp & 3;    // 4 warps over M (32 rows each)
    const int wn = warp >> 2;   // 2 warps over N (64 cols each)
    const int n0 = blockIdx.x * 128;
    const int m0 = blockIdx.y * 128;

    int lay, kc, t;
    if (blockIdx.z < KS1) {
        if (c == 0) return;
        lay = 1; kc = (int)blockIdx.z; t = c - 1;
    } else {
        if (c >= TT) return;
        lay = 0; kc = (int)blockIdx.z - KS1; t = c;
    }
    const int p = t & 1;
    const int sbeg = kc * SPC;

    const uint32_t sb0 = smem_u32(sm);

    // Stage loader: 256 threads, 4 cp.async(16B) each.
    // Thread -> (row = tid>>1, half = tid&1). hi at +0, lo at +32 in the row.
    const int lrow = tid >> 1;            // 0..127
    const int lhalf = tid & 1;            // which 8-half chunk
    auto load_stage = [&](int kt, int buf) {
        const __half *pAh, *pAl, *pBh, *pBl;
        int kk;
        if (lay == 0) {
            pAh = g_h0h[p]; pAl = g_h0l[p]; pBh = g_Whh0h; pBl = g_Whh0l;
            kk = kt * 16;
        } else if (kt < 128) {
            pAh = g_h0h[p ^ 1]; pAl = g_h0l[p ^ 1]; pBh = g_Wih1h; pBl = g_Wih1l;
            kk = kt * 16;
        } else {
            pAh = g_h1h[p]; pAl = g_h1l[p]; pBh = g_Whh1h; pBl = g_Whh1l;
            kk = (kt - 128) * 16;
        }
        const uint32_t sb = sb0 + (uint32_t)buf * STAGE_P;
        const uint32_t so = (uint32_t)(lrow * ROWB_P + lhalf * 16);   // 16-aligned
        const size_t gA = (size_t)(m0 + lrow) * HH + kk + lhalf * 8;
        const size_t gB = (size_t)(n0 + lrow) * HH + kk + lhalf * 8;
        cp16(sb + OFF_A + so,      pAh + gA);
        cp16(sb + OFF_A + so + 32, pAl + gA);
        cp16(sb + OFF_B + so,      pBh + gB);
        cp16(sb + OFF_B + so + 32, pBl + gB);
        asm volatile("cp.async.commit_group;\n" ::: "memory");
    };

    // ldmatrix lane address components (fragment layout validated since R4)
    const int rowA = (lane & 7) + ((lane >> 3) & 1) * 8;
    const int colA = (lane >> 4) * 8;       // halves -> bytes {0,16}: 16-aligned
    const int rowB = (lane & 7) + (lane >> 4) * 8;
    const int colB = ((lane >> 3) & 1) * 8;

    float acc[2][8][4];
#pragma unroll
    for (int i = 0; i < 2; i++)
#pragma unroll
        for (int j = 0; j < 8; j++)
#pragma unroll
            for (int k = 0; k < 4; k++) acc[i][j][k] = 0.0f;

    load_stage(sbeg, 0);
    load_stage(sbeg + 1, 1);

    for (int i = 0; i < SPC; i++) {
        const int buf = i & 1;
        if (i < SPC - 1) {
            asm volatile("cp.async.wait_group 1;\n" ::: "memory");
        } else {
            asm volatile("cp.async.wait_group 0;\n" ::: "memory");
        }
        __syncthreads();

        const uint32_t base = sb0 + (uint32_t)buf * STAGE_P;
        uint32_t ah[2][4], al[2][4];
#pragma unroll
        for (int mt = 0; mt < 2; mt++) {
            const uint32_t ao = (uint32_t)((wm * 32 + mt * 16 + rowA) * ROWB_P + colA * 2);
            ldsm4(ah[mt], base + OFF_A + ao);
            ldsm4(al[mt], base + OFF_A + ao + 32);
        }
#pragma unroll
        for (int ng = 0; ng < 4; ng++) {
            uint32_t bh[4], bl[4];
            const uint32_t bo = (uint32_t)((wn * 64 + ng * 16 + rowB) * ROWB_P + colB * 2);
            ldsm4(bh, base + OFF_B + bo);
            ldsm4(bl, base + OFF_B + bo + 32);
#pragma unroll
            for (int mt = 0; mt < 2; mt++)
#pragma unroll
                for (int h2 = 0; h2 < 2; h2++) {
                    float* a = acc[mt][ng * 2 + h2];
                    mma16(a, ah[mt], bh + h2 * 2);   // hi*hi
                    mma16(a, al[mt], bh + h2 * 2);   // lo*hi
                    mma16(a, ah[mt], bl + h2 * 2);   // hi*lo
                }
        }

        if (i + 2 < SPC) {
            __syncthreads();                 // all warps done with this buffer
            load_stage(sbeg + i + 2, buf);   // refill it
        }
    }

    // Write fp32 partial tile (no atomics; finisher reduces)
    float* P = lay ? g_part1[kc] : g_part0[kc];
#pragma unroll
    for (int mt = 0; mt < 2; mt++) {
#pragma unroll
        for (int hi = 0; hi < 2; hi++) {
            const int r = m0 + wm * 32 + mt * 16 + (lane >> 2) + hi * 8;
#pragma unroll
            for (int ng = 0; ng < 4; ng++)
#pragma unroll
                for (int h2 = 0; h2 < 2; h2++) {
                    const int cc = n0 + wn * 64 + ng * 16 + h2 * 8 + (lane & 3) * 2;
                    float2 v;
                    v.x = acc[mt][ng * 2 + h2][hi * 2 + 0];
                    v.y = acc[mt][ng * 2 + h2][hi * 2 + 1];
                    *(float2*)(P + (size_t)r * HH + cc) = v;
                }
        }
    }
}

// ---------------------------------------------------------------------------
// Finisher: fixed-order sum of split-K partials + epilogue. Deterministic.
// blockIdx.y == 0 -> lay1 (t=c-1), == 1 -> lay0 (t=c).
// ---------------------------------------------------------------------------
__global__ __launch_bounds__(256) void finisher_kernel(
    const int* __restrict__ tokens,
    const float* __restrict__ b_ih,
    const float* __restrict__ b_hh,
    int c)
{
    const int lay = (blockIdx.y == 0) ? 1 : 0;
    if (lay == 1 && c == 0) return;
    if (lay == 0 && c >= TT) return;
    const int t = lay ? (c - 1) : c;
    const int p = t & 1;

    const int gi = (blockIdx.x * 256 + threadIdx.x) * 4;   // over BB*HH
    if (gi >= BB * HH) return;
    const int r = gi / HH;
    const int col = gi % HH;

    float o[4];
    if (lay == 1) {
        float4 v = *(const float4*)(g_part1[0] + gi);
#pragma unroll
        for (int k = 1; k < KS1; k++) {
            const float4 q = *(const float4*)(g_part1[k] + gi);
            v.x += q.x; v.y += q.y; v.z += q.z; v.w += q.w;
        }
        o[0] = v.x; o[1] = v.y; o[2] = v.z; o[3] = v.w;
#pragma unroll
        for (int q = 0; q < 4; q++)
            o[q] += b_ih[HH + col + q] + b_hh[HH + col + q];
    } else {
        float4 v = *(const float4*)(g_part0[0] + gi);
#pragma unroll
        for (int k = 1; k < KS0; k++) {
            const float4 q = *(const float4*)(g_part0[k] + gi);
            v.x += q.x; v.y += q.y; v.z += q.z; v.w += q.w;
        }
        const int tok = tokens[r * TT + t];
        const float4 e = *(const float4*)(g_Eprime + (size_t)tok * HH + col);
        o[0] = v.x + e.x; o[1] = v.y + e.y; o[2] = v.z + e.z; o[3] = v.w + e.w;
    }

    __align__(8) __half hv[4];
    __align__(8) __half lv[4];
#pragma unroll
    for (int q = 0; q < 4; q++) {
        const float tv = my_tanh(o[q]);
        f16_split(tv, hv[q], lv[q]);
    }

    if (lay == 0) {
        *(uint64_t*)(g_h0h[p ^ 1] + gi) = *(const uint64_t*)hv;
        *(uint64_t*)(g_h0l[p ^ 1] + gi) = *(const uint64_t*)lv;
    } else {
        *(uint64_t*)(g_h1h[p ^ 1] + gi) = *(const uint64_t*)hv;
        *(uint64_t*)(g_h1l[p ^ 1] + gi) = *(const uint64_t*)lv;
        const size_t oidx = (size_t)t * BB * HH + gi;
        *(uint64_t*)(g_outsh + oidx) = *(const uint64_t*)hv;
        *(uint64_t*)(g_outsl + oidx) = *(const uint64_t*)lv;
    }
}

// ---------------------------------------------------------------------------
// Legacy mma kernel for EPRIME and LOGITS (off critical path; proven shape).
// BM=BN=64, BK=32, 256 threads, single acc (unscaled lo).
// ---------------------------------------------------------------------------
#define MODE_EPRIME 0
#define MODE_LOGITS 3
#define ROWB_G 80
#define STAGEB 5120

template <int MODE>
__global__ __launch_bounds__(256) void gemm_kernel(
    const float* __restrict__ b_ih,
    const float* __restrict__ b_hh,
    const float* __restrict__ fc_b,
    float* __restrict__ d_out)
{
    __shared__ __align__(16) __half Ash[2][64][40];
    __shared__ __align__(16) __half Asl[2][64][40];
    __shared__ __align__(16) __half Bsh[2][64][40];
    __shared__ __align__(16) __half Bsl[2][64][40];

    const __half *A0h, *A0l, *B0h, *B0l;
    int KT;
    if (MODE == MODE_EPRIME) {
        A0h = g_embh; A0l = g_embl; B0h = g_Wih0h; B0l = g_Wih0l; KT = 64;
    } else {
        A0h = g_outsh; A0l = g_outsl; B0h = g_fcwh; B0l = g_fcwl; KT = 64;
    }

    int m0, n0;
    if (MODE == MODE_LOGITS) { m0 = blockIdx.y * 64; n0 = blockIdx.x * 64; }
    else                     { m0 = blockIdx.x * 64; n0 = blockIdx.y * 64; }

    const int tid = threadIdx.x;
    const int lane = tid & 31;
    const int warp = tid >> 5;
    const int wm = warp & 1;
    const int wn = warp >> 1;

    const uint32_t smAh = smem_u32(&Ash[0][0][0]);
    const uint32_t smAl = smem_u32(&Asl[0][0][0]);
    const uint32_t smBh = smem_u32(&Bsh[0][0][0]);
    const uint32_t smBl = smem_u32(&Bsl[0][0][0]);

    const int rowA = (lane & 7) + ((lane >> 3) & 1) * 8;
    const int colA = (lane >> 4) * 8;
    const int rowB = (lane & 7) + (lane >> 4) * 8;
    const int colB = ((lane >> 3) & 1) * 8;
    const uint32_t aOffH = smAh + (uint32_t)((wm * 32 + rowA) * ROWB_G + colA * 2);
    const uint32_t aOffL = smAl + (uint32_t)((wm * 32 + rowA) * ROWB_G + colA * 2);
    const uint32_t bOffH = smBh + (uint32_t)((wn * 16 + rowB) * ROWB_G + colB * 2);
    const uint32_t bOffL = smBl + (uint32_t)((wn * 16 + rowB) * ROWB_G + colB * 2);

    float accc[2][2][4];
#pragma unroll
    for (int i = 0; i < 2; i++)
#pragma unroll
        for (int j = 0; j < 2; j++)
#pragma unroll
            for (int k = 0; k < 4; k++) accc[i][j][k] = 0.0f;

    const int lrow = tid >> 2;
    const int lc8 = (tid & 3) * 8;
    auto load_tile = [&](int kt, int s) {
        int kk = kt * 32;
        const size_t gA = (size_t)(m0 + lrow) * HH + kk + lc8;
        const size_t gB = (size_t)(n0 + lrow) * HH + kk + lc8;
        const uint32_t so = (uint32_t)(s * STAGEB + lrow * ROWB_G + lc8 * 2);
        cp16(smAh + so, A0h + gA);
        cp16(smAl + so, A0l + gA);
        cp16(smBh + so, B0h + gB);
        cp16(smBl + so, B0l + gB);
        asm volatile("cp.async.commit_group;\n" ::: "memory");
    };

    load_tile(0, 0);

    for (int kt = 0; kt < KT; kt++) {
        const int s = kt & 1;
        asm volatile("cp.async.wait_group 0;\n" ::: "memory");
        __syncthreads();
        if (kt + 1 < KT) load_tile(kt + 1, s ^ 1);

        const uint32_t sb = (uint32_t)(s * STAGEB);
#pragma unroll
        for (int ks = 0; ks < 2; ks++) {
            uint32_t ah[2][4], al[2][4], bh[4], bl[4];
            const uint32_t ko = (uint32_t)(ks * 32);
#pragma unroll
            for (int mt = 0; mt < 2; mt++) {
                ldsm4(ah[mt], aOffH + sb + (uint32_t)(mt * 16 * ROWB_G) + ko);
                ldsm4(al[mt], aOffL + sb + (uint32_t)(mt * 16 * ROWB_G) + ko);
            }
            ldsm4(bh, bOffH + sb + ko);
            ldsm4(bl, bOffL + sb + ko);
#pragma unroll
            for (int mt = 0; mt < 2; mt++)
#pragma unroll
                for (int nt = 0; nt < 2; nt++) {
                    mma16(accc[mt][nt], ah[mt], bh + nt * 2);
                    mma16(accc[mt][nt], al[mt], bh + nt * 2);
                    mma16(accc[mt][nt], ah[mt], bl + nt * 2);
                }
        }
    }

#pragma unroll
    for (int mt = 0; mt < 2; mt++) {
#pragma unroll
        for (int hi = 0; hi < 2; hi++) {
            const int r = m0 + wm * 32 + mt * 16 + (lane >> 2) + hi * 8;
#pragma unroll
            for (int nt = 0; nt < 2; nt++) {
#pragma unroll
                for (int lo = 0; lo < 2; lo++) {
                    const int cc = n0 + wn * 16 + nt * 8 + (lane & 3) * 2 + lo;
                    float v = accc[mt][nt][hi * 2 + lo];
                    if (MODE == MODE_EPRIME) {
                        v += b_ih[cc] + b_hh[cc];
                        g_Eprime[(size_t)r * HH + cc] = v;
                    } else {
                        v += fc_b[cc];
                        d_out[(size_t)r * VV + cc] = v;
                    }
                }
            }
        }
    }
}

// ---------------------------------------------------------------------------
// h_final (last step wrote parity 0; h = hi + lo, unscaled)
// ---------------------------------------------------------------------------
__global__ void final_copy_kernel(float* __restrict__ d_out) {
    int i = blockIdx.x * blockDim.x + threadIdx.x;
    if (i < BB * HH) {
        d_out[(size_t)TT * BB * VV + i] =
            __half2float(g_h0h[0][i]) + __half2float(g_h0l[0][i]);
        d_out[(size_t)TT * BB * VV + BB * HH + i] =
            __half2float(g_h1h[0][i]) + __half2float(g_h1l[0][i]);
    }
}

// ---------------------------------------------------------------------------
// Launch
// ---------------------------------------------------------------------------
extern "C" void kernel_launch(void* const* d_in, const int* in_sizes, int n_in,
                              void* d_out, int out_size) {
    const int*   tokens = (const int*)d_in[0];
    const float* h0     = (const float*)d_in[1];
    const float* emb    = (const float*)d_in[2];
    const float* Wih    = (const float*)d_in[3];
    const float* Whh    = (const float*)d_in[4];
    const float* bih    = (const float*)d_in[5];
    const float* bhh    = (const float*)d_in[6];
    const float* fcw    = (const float*)d_in[7];
    const float* fcb    = (const float*)d_in[8];
    float* out = (float*)d_out;

    // 1) Split weights + initial state into fp16 hi/lo
    prep_kernel<<<1024, 256>>>(h0, emb, Wih, Whh, fcw);

    // 2) E'' = emb @ W_ih0^T + b_ih0 + b_hh0
    gemm_kernel<MODE_EPRIME><<<dim3(VV / 64, HH / 64), 256>>>(bih, bhh, fcb, out);

    // 3) Recurrence: 201 pair launches + finishers.
    //    Launch c: partials for step1(c-1) || step0(c), then reduce+activate.
    for (int c = 0; c <= TT; c++) {
        pair_gemm_kernel<<<dim3(16, 2, KS1 + KS0), 256>>>(c);
        finisher_kernel<<<dim3(BB * HH / 1024, 2), 256>>>(tokens, bih, bhh, c);
    }

    // 4) Logits: [T*B, H] @ [V, H]^T + fc_b
    gemm_kernel<MODE_LOGITS><<<dim3(VV / 64, (TT * BB) / 64), 256>>>(bih, bhh, fcb, out);

    // 5) h_final
    if (out_size >= TT * BB * VV + LL * BB * HH)
        final_copy_kernel<<<(BB * HH + 255) / 256, 256>>>(out);
}

// round 13
// speedup vs baseline: 1.3804x; 1.0078x over previous
#include <cuda_runtime.h>
#include <cuda_fp16.h>
#include <cstdint>
#include <cstddef>

// Problem constants
#define HH 2048
#define BB 256
#define TT 200
#define VV 512
#define LL 2

// ---------------------------------------------------------------------------
// Scratch (static __device__ — no allocations allowed)
// Operands stored as fp16 (hi, lo) pairs, lo UNSCALED (subnormals OK).
// ---------------------------------------------------------------------------
__device__ __align__(128) __half g_Wih0h[HH * HH];
__device__ __align__(128) __half g_Wih0l[HH * HH];
__device__ __align__(128) __half g_Whh0h[HH * HH];
__device__ __align__(128) __half g_Whh0l[HH * HH];
__device__ __align__(128) __half g_Wih1h[HH * HH];
__device__ __align__(128) __half g_Wih1l[HH * HH];
__device__ __align__(128) __half g_Whh1h[HH * HH];
__device__ __align__(128) __half g_Whh1l[HH * HH];
__device__ __align__(128) __half g_embh[VV * HH];
__device__ __align__(128) __half g_embl[VV * HH];
__device__ __align__(128) __half g_fcwh[VV * HH];
__device__ __align__(128) __half g_fcwl[VV * HH];
__device__ __align__(128) float  g_Eprime[VV * HH];
__device__ __align__(128) __half g_h0h[2][BB * HH];
__device__ __align__(128) __half g_h0l[2][BB * HH];
__device__ __align__(128) __half g_h1h[2][BB * HH];
__device__ __align__(128) __half g_h1l[2][BB * HH];
__device__ __align__(128) __half g_outsh[(size_t)TT * BB * HH];
__device__ __align__(128) __half g_outsl[(size_t)TT * BB * HH];

// Split-K partial accumulators (fp32); reduced by a separate finisher kernel.
#define KS1 8
#define KS0 4
__device__ __align__(128) float g_part1[KS1][BB * HH];
__device__ __align__(128) float g_part0[KS0][BB * HH];

// ---------------------------------------------------------------------------
// Helpers
// ---------------------------------------------------------------------------
__device__ __forceinline__ void f16_split(float x, __half& hi, __half& lo) {
    __half h = __float2half_rn(x);
    hi = h;
    lo = __float2half_rn(x - __half2float(h));   // unscaled residual
}

// tanh immune to --use_fast_math's tanh.approx (too inaccurate).
__device__ __forceinline__ float my_tanh(float x) {
    float e = __expf(2.0f * x);
    return 1.0f - 2.0f / (e + 1.0f);
}

__device__ __forceinline__ void cp16(uint32_t smem_addr, const void* src) {
    asm volatile("cp.async.cg.shared.global [%0], [%1], 16;\n"
                 :: "r"(smem_addr), "l"(src));
}

__device__ __forceinline__ void ldsm4(uint32_t* r, uint32_t addr) {
    asm volatile("ldmatrix.sync.aligned.m8n8.x4.shared.b16 {%0,%1,%2,%3}, [%4];\n"
                 : "=r"(r[0]), "=r"(r[1]), "=r"(r[2]), "=r"(r[3])
                 : "r"(addr));
}

__device__ __forceinline__ void mma16(float* c, const uint32_t* a, const uint32_t* b) {
    asm volatile(
        "mma.sync.aligned.m16n8k16.row.col.f32.f16.f16.f32 "
        "{%0,%1,%2,%3}, {%4,%5,%6,%7}, {%8,%9}, {%0,%1,%2,%3};\n"
        : "+f"(c[0]), "+f"(c[1]), "+f"(c[2]), "+f"(c[3])
        : "r"(a[0]), "r"(a[1]), "r"(a[2]), "r"(a[3]),
          "r"(b[0]), "r"(b[1]));
}

__device__ __forceinline__ uint32_t smem_u32(const void* p) {
    return (uint32_t)__cvta_generic_to_shared(p);
}

// ---------------------------------------------------------------------------
// Prep: split all weights + initial hidden state into fp16 hi/lo
// ---------------------------------------------------------------------------
__global__ void prep_kernel(const float* __restrict__ h0,
                            const float* __restrict__ emb,
                            const float* __restrict__ Wih,
                            const float* __restrict__ Whh,
                            const float* __restrict__ fcw) {
    int idx = blockIdx.x * blockDim.x + threadIdx.x;
    int stride = gridDim.x * blockDim.x;
    for (int i = idx; i < HH * HH; i += stride) {
        f16_split(Wih[i],           g_Wih0h[i], g_Wih0l[i]);
        f16_split(Wih[HH * HH + i], g_Wih1h[i], g_Wih1l[i]);
        f16_split(Whh[i],           g_Whh0h[i], g_Whh0l[i]);
        f16_split(Whh[HH * HH + i], g_Whh1h[i], g_Whh1l[i]);
    }
    for (int i = idx; i < VV * HH; i += stride) {
        f16_split(emb[i], g_embh[i], g_embl[i]);
        f16_split(fcw[i], g_fcwh[i], g_fcwl[i]);
    }
    for (int i = idx; i < BB * HH; i += stride) {
        f16_split(h0[i],           g_h0h[0][i], g_h0l[0][i]);
        f16_split(h0[BB * HH + i], g_h1h[0][i], g_h1l[0][i]);
    }
}

// ---------------------------------------------------------------------------
// Pair GEMM with split-K (partials only; reduction in finisher_kernel).
// Launch c computes:
//   lay=1 (z 0..7):  step1(c-1) partials: h0'@Wih1^T + h1@Whh1^T, K=4096
//   lay=0 (z 8..11): step0(c)   partials: h0 @Whh0^T,             K=2048
// CTA tile BM=128, BN=128, BK=16, 2-stage STATIC smem (40 KB), 256 threads
// = 8 warps (4M x 2N), warp region 32x64, single fp32 acc, 3 mma passes.
// Smem row (80 B, 16-aligned, conflict-free): [16 hi halves|16 lo halves|pad].
// Each k-chunk = 32 stages of BK=16.
// ---------------------------------------------------------------------------
#define ROWB_P 80                 // bytes per smem row
#define ARR_P  (128 * ROWB_P)     // 10240 B per operand (A or B)
#define STAGE_P (2 * ARR_P)       // 20480 B per stage
#define OFF_A 0
#define OFF_B ARR_P
#define SPC 32                    // stages per k-chunk

__global__ __launch_bounds__(256, 2) void pair_gemm_kernel(int c)
{
    __shared__ __align__(16) char sm[2 * STAGE_P];   // 40960 B, static

    const int tid = threadIdx.x;
    const int lane = tid & 31;
    const int warp = tid >> 5;
    const int wm = warp & 3;    // 4 warps over M (32 rows each)
    const int wn = warp >> 2;   // 2 warps over N (64 cols each)
    const int n0 = blockIdx.x * 128;
    const int m0 = blockIdx.y * 128;

    int lay, kc, t;
    if (blockIdx.z < KS1) {
        if (c == 0) return;
        lay = 1; kc = (int)blockIdx.z; t = c - 1;
    } else {
        if (c >= TT) return;
        lay = 0; kc = (int)blockIdx.z - KS1; t = c;
    }
    const int p = t & 1;
    const int sbeg = kc * SPC;

    const uint32_t sb0 = smem_u32(sm);

    // Stage loader: 256 threads, 4 cp.async(16B) each.
    // Thread -> (row = tid>>1, half = tid&1). hi at +0, lo at +32 in the row.
    const int lrow = tid >> 1;            // 0..127
    const int lhalf = tid & 1;            // which 8-half chunk
    auto load_stage = [&](int kt, int buf) {
        const __half *pAh, *pAl, *pBh, *pBl;
        int kk;
        if (lay == 0) {
            pAh = g_h0h[p]; pAl = g_h0l[p]; pBh = g_Whh0h; pBl = g_Whh0l;
            kk = kt * 16;
        } else if (kt < 128) {
            pAh = g_h0h[p ^ 1]; pAl = g_h0l[p ^ 1]; pBh = g_Wih1h; pBl = g_Wih1l;
            kk = kt * 16;
        } else {
            pAh = g_h1h[p]; pAl = g_h1l[p]; pBh = g_Whh1h; pBl = g_Whh1l;
            kk = (kt - 128) * 16;
        }
        const uint32_t sb = sb0 + (uint32_t)buf * STAGE_P;
        const uint32_t so = (uint32_t)(lrow * ROWB_P + lhalf * 16);   // 16-aligned
        const size_t gA = (size_t)(m0 + lrow) * HH + kk + lhalf * 8;
        const size_t gB = (size_t)(n0 + lrow) * HH + kk + lhalf * 8;
        cp16(sb + OFF_A + so,      pAh + gA);
        cp16(sb + OFF_A + so + 32, pAl + gA);
        cp16(sb + OFF_B + so,      pBh + gB);
        cp16(sb + OFF_B + so + 32, pBl + gB);
        asm volatile("cp.async.commit_group;\n" ::: "memory");
    };

    // ldmatrix lane address components (fragment layout validated since R4)
    const int rowA = (lane & 7) + ((lane >> 3) & 1) * 8;
    const int colA = (lane >> 4) * 8;       // halves -> bytes {0,16}: 16-aligned
    const int rowB = (lane & 7) + (lane >> 4) * 8;
    const int colB = ((lane >> 3) & 1) * 8;

    float acc[2][8][4];
#pragma unroll
    for (int i = 0; i < 2; i++)
#pragma unroll
        for (int j = 0; j < 8; j++)
#pragma unroll
            for (int k = 0; k < 4; k++) acc[i][j][k] = 0.0f;

    load_stage(sbeg, 0);
    load_stage(sbeg + 1, 1);

    for (int i = 0; i < SPC; i++) {
        const int buf = i & 1;
        if (i < SPC - 1) {
            asm volatile("cp.async.wait_group 1;\n" ::: "memory");
        } else {
            asm volatile("cp.async.wait_group 0;\n" ::: "memory");
        }
        __syncthreads();

        const uint32_t base = sb0 + (uint32_t)buf * STAGE_P;
        uint32_t ah[2][4], al[2][4];
#pragma unroll
        for (int mt = 0; mt < 2; mt++) {
            const uint32_t ao = (uint32_t)((wm * 32 + mt * 16 + rowA) * ROWB_P + colA * 2);
            ldsm4(ah[mt], base + OFF_A + ao);
            ldsm4(al[mt], base + OFF_A + ao + 32);
        }
#pragma unroll
        for (int ng = 0; ng < 4; ng++) {
            uint32_t bh[4], bl[4];
            const uint32_t bo = (uint32_t)((wn * 64 + ng * 16 + rowB) * ROWB_P + colB * 2);
            ldsm4(bh, base + OFF_B + bo);
            ldsm4(bl, base + OFF_B + bo + 32);
#pragma unroll
            for (int mt = 0; mt < 2; mt++)
#pragma unroll
                for (int h2 = 0; h2 < 2; h2++) {
                    float* a = acc[mt][ng * 2 + h2];
                    mma16(a, ah[mt], bh + h2 * 2);   // hi*hi
                    mma16(a, al[mt], bh + h2 * 2);   // lo*hi
                    mma16(a, ah[mt], bl + h2 * 2);   // hi*lo
                }
        }

        if (i + 2 < SPC) {
            __syncthreads();                 // all warps done with this buffer
            load_stage(sbeg + i + 2, buf);   // refill it
        }
    }

    // Write fp32 partial tile (no atomics; finisher reduces)
    float* P = lay ? g_part1[kc] : g_part0[kc];
#pragma unroll
    for (int mt = 0; mt < 2; mt++) {
#pragma unroll
        for (int hi = 0; hi < 2; hi++) {
            const int r = m0 + wm * 32 + mt * 16 + (lane >> 2) + hi * 8;
#pragma unroll
            for (int ng = 0; ng < 4; ng++)
#pragma unroll
                for (int h2 = 0; h2 < 2; h2++) {
                    const int cc = n0 + wn * 64 + ng * 16 + h2 * 8 + (lane & 3) * 2;
                    float2 v;
                    v.x = acc[mt][ng * 2 + h2][hi * 2 + 0];
                    v.y = acc[mt][ng * 2 + h2][hi * 2 + 1];
                    *(float2*)(P + (size_t)r * HH + cc) = v;
                }
        }
    }
}

// ---------------------------------------------------------------------------
// Finisher: fixed-order sum of split-K partials + epilogue. Deterministic.
// blockIdx.y == 0 -> lay1 (t=c-1), == 1 -> lay0 (t=c).
// ---------------------------------------------------------------------------
__global__ __launch_bounds__(256) void finisher_kernel(
    const int* __restrict__ tokens,
    const float* __restrict__ b_ih,
    const float* __restrict__ b_hh,
    int c)
{
    const int lay = (blockIdx.y == 0) ? 1 : 0;
    if (lay == 1 && c == 0) return;
    if (lay == 0 && c >= TT) return;
    const int t = lay ? (c - 1) : c;
    const int p = t & 1;

    const int gi = (blockIdx.x * 256 + threadIdx.x) * 4;   // over BB*HH
    if (gi >= BB * HH) return;
    const int r = gi / HH;
    const int col = gi % HH;

    float o[4];
    if (lay == 1) {
        float4 v = *(const float4*)(g_part1[0] + gi);
#pragma unroll
        for (int k = 1; k < KS1; k++) {
            const float4 q = *(const float4*)(g_part1[k] + gi);
            v.x += q.x; v.y += q.y; v.z += q.z; v.w += q.w;
        }
        o[0] = v.x; o[1] = v.y; o[2] = v.z; o[3] = v.w;
#pragma unroll
        for (int q = 0; q < 4; q++)
            o[q] += b_ih[HH + col + q] + b_hh[HH + col + q];
    } else {
        float4 v = *(const float4*)(g_part0[0] + gi);
#pragma unroll
        for (int k = 1; k < KS0; k++) {
            const float4 q = *(const float4*)(g_part0[k] + gi);
            v.x += q.x; v.y += q.y; v.z += q.z; v.w += q.w;
        }
        const int tok = tokens[r * TT + t];
        const float4 e = *(const float4*)(g_Eprime + (size_t)tok * HH + col);
        o[0] = v.x + e.x; o[1] = v.y + e.y; o[2] = v.z + e.z; o[3] = v.w + e.w;
    }

    __align__(8) __half hv[4];
    __align__(8) __half lv[4];
#pragma unroll
    for (int q = 0; q < 4; q++) {
        const float tv = my_tanh(o[q]);
        f16_split(tv, hv[q], lv[q]);
    }

    if (lay == 0) {
        *(uint64_t*)(g_h0h[p ^ 1] + gi) = *(const uint64_t*)hv;
        *(uint64_t*)(g_h0l[p ^ 1] + gi) = *(const uint64_t*)lv;
    } else {
        *(uint64_t*)(g_h1h[p ^ 1] + gi) = *(const uint64_t*)hv;
        *(uint64_t*)(g_h1l[p ^ 1] + gi) = *(const uint64_t*)lv;
        const size_t oidx = (size_t)t * BB * HH + gi;
        *(uint64_t*)(g_outsh + oidx) = *(const uint64_t*)hv;
        *(uint64_t*)(g_outsl + oidx) = *(const uint64_t*)lv;
    }
}

// ---------------------------------------------------------------------------
// Legacy mma kernel for EPRIME and LOGITS (off critical path; proven shape).
// BM=BN=64, BK=32, 256 threads, single acc (unscaled lo).
// ---------------------------------------------------------------------------
#define MODE_EPRIME 0
#define MODE_LOGITS 3
#define ROWB_G 80
#define STAGEB 5120

template <int MODE>
__global__ __launch_bounds__(256) void gemm_kernel(
    const float* __restrict__ b_ih,
    const float* __restrict__ b_hh,
    const float* __restrict__ fc_b,
    float* __restrict__ d_out)
{
    __shared__ __align__(16) __half Ash[2][64][40];
    __shared__ __align__(16) __half Asl[2][64][40];
    __shared__ __align__(16) __half Bsh[2][64][40];
    __shared__ __align__(16) __half Bsl[2][64][40];

    const __half *A0h, *A0l, *B0h, *B0l;
    int KT;
    if (MODE == MODE_EPRIME) {
        A0h = g_embh; A0l = g_embl; B0h = g_Wih0h; B0l = g_Wih0l; KT = 64;
    } else {
        A0h = g_outsh; A0l = g_outsl; B0h = g_fcwh; B0l = g_fcwl; KT = 64;
    }

    int m0, n0;
    if (MODE == MODE_LOGITS) { m0 = blockIdx.y * 64; n0 = blockIdx.x * 64; }
    else                     { m0 = blockIdx.x * 64; n0 = blockIdx.y * 64; }

    const int tid = threadIdx.x;
    const int lane = tid & 31;
    const int warp = tid >> 5;
    const int wm = warp & 1;
    const int wn = warp >> 1;

    const uint32_t smAh = smem_u32(&Ash[0][0][0]);
    const uint32_t smAl = smem_u32(&Asl[0][0][0]);
    const uint32_t smBh = smem_u32(&Bsh[0][0][0]);
    const uint32_t smBl = smem_u32(&Bsl[0][0][0]);

    const int rowA = (lane & 7) + ((lane >> 3) & 1) * 8;
    const int colA = (lane >> 4) * 8;
    const int rowB = (lane & 7) + (lane >> 4) * 8;
    const int colB = ((lane >> 3) & 1) * 8;
    const uint32_t aOffH = smAh + (uint32_t)((wm * 32 + rowA) * ROWB_G + colA * 2);
    const uint32_t aOffL = smAl + (uint32_t)((wm * 32 + rowA) * ROWB_G + colA * 2);
    const uint32_t bOffH = smBh + (uint32_t)((wn * 16 + rowB) * ROWB_G + colB * 2);
    const uint32_t bOffL = smBl + (uint32_t)((wn * 16 + rowB) * ROWB_G + colB * 2);

    float accc[2][2][4];
#pragma unroll
    for (int i = 0; i < 2; i++)
#pragma unroll
        for (int j = 0; j < 2; j++)
#pragma unroll
            for (int k = 0; k < 4; k++) accc[i][j][k] = 0.0f;

    const int lrow = tid >> 2;
    const int lc8 = (tid & 3) * 8;
    auto load_tile = [&](int kt, int s) {
        int kk = kt * 32;
        const size_t gA = (size_t)(m0 + lrow) * HH + kk + lc8;
        const size_t gB = (size_t)(n0 + lrow) * HH + kk + lc8;
        const uint32_t so = (uint32_t)(s * STAGEB + lrow * ROWB_G + lc8 * 2);
        cp16(smAh + so, A0h + gA);
        cp16(smAl + so, A0l + gA);
        cp16(smBh + so, B0h + gB);
        cp16(smBl + so, B0l + gB);
        asm volatile("cp.async.commit_group;\n" ::: "memory");
    };

    load_tile(0, 0);

    for (int kt = 0; kt < KT; kt++) {
        const int s = kt & 1;
        asm volatile("cp.async.wait_group 0;\n" ::: "memory");
        __syncthreads();
        if (kt + 1 < KT) load_tile(kt + 1, s ^ 1);

        const uint32_t sb = (uint32_t)(s * STAGEB);
#pragma unroll
        for (int ks = 0; ks < 2; ks++) {
            uint32_t ah[2][4], al[2][4], bh[4], bl[4];
            const uint32_t ko = (uint32_t)(ks * 32);
#pragma unroll
            for (int mt = 0; mt < 2; mt++) {
                ldsm4(ah[mt], aOffH + sb + (uint32_t)(mt * 16 * ROWB_G) + ko);
                ldsm4(al[mt], aOffL + sb + (uint32_t)(mt * 16 * ROWB_G) + ko);
            }
            ldsm4(bh, bOffH + sb + ko);
            ldsm4(bl, bOffL + sb + ko);
#pragma unroll
            for (int mt = 0; mt < 2; mt++)
#pragma unroll
                for (int nt = 0; nt < 2; nt++) {
                    mma16(accc[mt][nt], ah[mt], bh + nt * 2);
                    mma16(accc[mt][nt], al[mt], bh + nt * 2);
                    mma16(accc[mt][nt], ah[mt], bl + nt * 2);
                }
        }
    }

#pragma unroll
    for (int mt = 0; mt < 2; mt++) {
#pragma unroll
        for (int hi = 0; hi < 2; hi++) {
            const int r = m0 + wm * 32 + mt * 16 + (lane >> 2) + hi * 8;
#pragma unroll
            for (int nt = 0; nt < 2; nt++) {
#pragma unroll
                for (int lo = 0; lo < 2; lo++) {
                    const int cc = n0 + wn * 16 + nt * 8 + (lane & 3) * 2 + lo;
                    float v = accc[mt][nt][hi * 2 + lo];
                    if (MODE == MODE_EPRIME) {
                        v += b_ih[cc] + b_hh[cc];
                        g_Eprime[(size_t)r * HH + cc] = v;
                    } else {
                        v += fc_b[cc];
                        d_out[(size_t)r * VV + cc] = v;
                    }
                }
            }
        }
    }
}

// ---------------------------------------------------------------------------
// h_final (last step wrote parity 0; h = hi + lo, unscaled)
// ---------------------------------------------------------------------------
__global__ void final_copy_kernel(float* __restrict__ d_out) {
    int i = blockIdx.x * blockDim.x + threadIdx.x;
    if (i < BB * HH) {
        d_out[(size_t)TT * BB * VV + i] =
            __half2float(g_h0h[0][i]) + __half2float(g_h0l[0][i]);
        d_out[(size_t)TT * BB * VV + BB * HH + i] =
            __half2float(g_h1h[0][i]) + __half2float(g_h1l[0][i]);
    }
}

// ---------------------------------------------------------------------------
// Launch
// ---------------------------------------------------------------------------
extern "C" void kernel_launch(void* const* d_in, const int* in_sizes, int n_in,
                              void* d_out, int out_size) {
    const int*   tokens = (const int*)d_in[0];
    const float* h0     = (const float*)d_in[1];
    const float* emb    = (const float*)d_in[2];
    const float* Wih    = (const float*)d_in[3];
    const float* Whh    = (const float*)d_in[4];
    const float* bih    = (const float*)d_in[5];
    const float* bhh    = (const float*)d_in[6];
    const float* fcw    = (const float*)d_in[7];
    const float* fcb    = (const float*)d_in[8];
    float* out = (float*)d_out;

    // 1) Split weights + initial state into fp16 hi/lo
    prep_kernel<<<1024, 256>>>(h0, emb, Wih, Whh, fcw);

    // 2) E'' = emb @ W_ih0^T + b_ih0 + b_hh0
    gemm_kernel<MODE_EPRIME><<<dim3(VV / 64, HH / 64), 256>>>(bih, bhh, fcb, out);

    // 3) Recurrence: 201 pair launches + finishers.
    //    Launch c: partials for step1(c-1) || step0(c), then reduce+activate.
    for (int c = 0; c <= TT; c++) {
        pair_gemm_kernel<<<dim3(16, 2, KS1 + KS0), 256>>>(c);
        finisher_kernel<<<dim3(BB * HH / 1024, 2), 256>>>(tokens, bih, bhh, c);
    }

    // 4) Logits: [T*B, H] @ [V, H]^T + fc_b
    gemm_kernel<MODE_LOGITS><<<dim3(VV / 64, (TT * BB) / 64), 256>>>(bih, bhh, fcb, out);

    // 5) h_final
    if (out_size >= TT * BB * VV + LL * BB * HH)
        final_copy_kernel<<<(BB * HH + 255) / 256, 256>>>(out);
}

// round 14
// speedup vs baseline: 1.6097x; 1.1661x over previous
#include <cuda_runtime.h>
#include <cuda_fp16.h>
#include <cstdint>
#include <cstddef>

// Problem constants
#define HH 2048
#define BB 256
#define TT 200
#define VV 512
#define LL 2

// ---------------------------------------------------------------------------
// Scratch (static __device__ — no allocations allowed)
// Operands stored as fp16 (hi, lo) pairs, lo UNSCALED (subnormals OK).
// ---------------------------------------------------------------------------
__device__ __align__(128) __half g_Wih0h[HH * HH];
__device__ __align__(128) __half g_Wih0l[HH * HH];
__device__ __align__(128) __half g_Whh0h[HH * HH];
__device__ __align__(128) __half g_Whh0l[HH * HH];
__device__ __align__(128) __half g_Wih1h[HH * HH];
__device__ __align__(128) __half g_Wih1l[HH * HH];
__device__ __align__(128) __half g_Whh1h[HH * HH];
__device__ __align__(128) __half g_Whh1l[HH * HH];
__device__ __align__(128) __half g_embh[VV * HH];
__device__ __align__(128) __half g_embl[VV * HH];
__device__ __align__(128) __half g_fcwh[VV * HH];
__device__ __align__(128) __half g_fcwl[VV * HH];
__device__ __align__(128) float  g_Eprime[VV * HH];
__device__ __align__(128) __half g_h0h[2][BB * HH];
__device__ __align__(128) __half g_h0l[2][BB * HH];
__device__ __align__(128) __half g_h1h[2][BB * HH];
__device__ __align__(128) __half g_h1l[2][BB * HH];
__device__ __align__(128) __half g_outsh[(size_t)TT * BB * HH];
__device__ __align__(128) __half g_outsl[(size_t)TT * BB * HH];

// Split-K partial accumulators (fp32); reduced by a separate finisher kernel.
// 6 + 3 chunks -> grid 16*2*9 = 288 CTAs = exactly one wave at occ 2.
#define KS1 6
#define KS0 3
__device__ __align__(128) float g_part1[KS1][BB * HH];
__device__ __align__(128) float g_part0[KS0][BB * HH];

// Stage counts (BK=16): lay1 K=4096 -> 256 stages; lay0 K=2048 -> 128 stages.
#define S1 256
#define S0 128

// ---------------------------------------------------------------------------
// Helpers
// ---------------------------------------------------------------------------
__device__ __forceinline__ void f16_split(float x, __half& hi, __half& lo) {
    __half h = __float2half_rn(x);
    hi = h;
    lo = __float2half_rn(x - __half2float(h));   // unscaled residual
}

// tanh immune to --use_fast_math's tanh.approx (too inaccurate).
__device__ __forceinline__ float my_tanh(float x) {
    float e = __expf(2.0f * x);
    return 1.0f - 2.0f / (e + 1.0f);
}

__device__ __forceinline__ void cp16(uint32_t smem_addr, const void* src) {
    asm volatile("cp.async.cg.shared.global [%0], [%1], 16;\n"
                 :: "r"(smem_addr), "l"(src));
}

__device__ __forceinline__ void ldsm4(uint32_t* r, uint32_t addr) {
    asm volatile("ldmatrix.sync.aligned.m8n8.x4.shared.b16 {%0,%1,%2,%3}, [%4];\n"
                 : "=r"(r[0]), "=r"(r[1]), "=r"(r[2]), "=r"(r[3])
                 : "r"(addr));
}

__device__ __forceinline__ void mma16(float* c, const uint32_t* a, const uint32_t* b) {
    asm volatile(
        "mma.sync.aligned.m16n8k16.row.col.f32.f16.f16.f32 "
        "{%0,%1,%2,%3}, {%4,%5,%6,%7}, {%8,%9}, {%0,%1,%2,%3};\n"
        : "+f"(c[0]), "+f"(c[1]), "+f"(c[2]), "+f"(c[3])
        : "r"(a[0]), "r"(a[1]), "r"(a[2]), "r"(a[3]),
          "r"(b[0]), "r"(b[1]));
}

__device__ __forceinline__ uint32_t smem_u32(const void* p) {
    return (uint32_t)__cvta_generic_to_shared(p);
}

// ---------------------------------------------------------------------------
// Prep: split all weights + initial hidden state into fp16 hi/lo
// ---------------------------------------------------------------------------
__global__ void prep_kernel(const float* __restrict__ h0,
                            const float* __restrict__ emb,
                            const float* __restrict__ Wih,
                            const float* __restrict__ Whh,
                            const float* __restrict__ fcw) {
    int idx = blockIdx.x * blockDim.x + threadIdx.x;
    int stride = gridDim.x * blockDim.x;
    for (int i = idx; i < HH * HH; i += stride) {
        f16_split(Wih[i],           g_Wih0h[i], g_Wih0l[i]);
        f16_split(Wih[HH * HH + i], g_Wih1h[i], g_Wih1l[i]);
        f16_split(Whh[i],           g_Whh0h[i], g_Whh0l[i]);
        f16_split(Whh[HH * HH + i], g_Whh1h[i], g_Whh1l[i]);
    }
    for (int i = idx; i < VV * HH; i += stride) {
        f16_split(emb[i], g_embh[i], g_embl[i]);
        f16_split(fcw[i], g_fcwh[i], g_fcwl[i]);
    }
    for (int i = idx; i < BB * HH; i += stride) {
        f16_split(h0[i],           g_h0h[0][i], g_h0l[0][i]);
        f16_split(h0[BB * HH + i], g_h1h[0][i], g_h1l[0][i]);
    }
}

// ---------------------------------------------------------------------------
// Pair GEMM with split-K (partials only; reduction in finisher_kernel).
// Launch c computes:
//   lay=1 (z 0..5): step1(c-1) partials: h0'@Wih1^T + h1@Whh1^T, K=4096
//   lay=0 (z 6..8): step0(c)   partials: h0 @Whh0^T,             K=2048
// CTA tile BM=128, BN=128, BK=16, 2-stage STATIC smem (40 KB), 256 threads
// = 8 warps (4M x 2N), warp region 32x64, single fp32 acc, 3 mma passes.
// Smem row (80 B, 16-aligned, conflict-free): [16 hi halves|16 lo halves|pad].
// k-chunks are (S*kc)/KS .. (S*(kc+1))/KS stages (uneven 42/43; lay1 seam at
// stage 128 falls exactly on the chunk-3 boundary).
// ---------------------------------------------------------------------------
#define ROWB_P 80                 // bytes per smem row
#define ARR_P  (128 * ROWB_P)     // 10240 B per operand (A or B)
#define STAGE_P (2 * ARR_P)       // 20480 B per stage
#define OFF_A 0
#define OFF_B ARR_P

__global__ __launch_bounds__(256, 2) void pair_gemm_kernel(int c)
{
    __shared__ __align__(16) char sm[2 * STAGE_P];   // 40960 B, static

    const int tid = threadIdx.x;
    const int lane = tid & 31;
    const int warp = tid >> 5;
    const int wm = warp & 3;    // 4 warps over M (32 rows each)
    const int wn = warp >> 2;   // 2 warps over N (64 cols each)
    const int n0 = blockIdx.x * 128;
    const int m0 = blockIdx.y * 128;

    int lay, kc, t, sbeg, send;
    if (blockIdx.z < KS1) {
        if (c == 0) return;
        lay = 1; kc = (int)blockIdx.z; t = c - 1;
        sbeg = (S1 * kc) / KS1; send = (S1 * (kc + 1)) / KS1;
    } else {
        if (c >= TT) return;
        lay = 0; kc = (int)blockIdx.z - KS1; t = c;
        sbeg = (S0 * kc) / KS0; send = (S0 * (kc + 1)) / KS0;
    }
    const int p = t & 1;
    const int nst = send - sbeg;

    const uint32_t sb0 = smem_u32(sm);

    // Stage loader: 256 threads, 4 cp.async(16B) each.
    // Thread -> (row = tid>>1, half = tid&1). hi at +0, lo at +32 in the row.
    const int lrow = tid >> 1;            // 0..127
    const int lhalf = tid & 1;            // which 8-half chunk
    auto load_stage = [&](int kt, int buf) {
        const __half *pAh, *pAl, *pBh, *pBl;
        int kk;
        if (lay == 0) {
            pAh = g_h0h[p]; pAl = g_h0l[p]; pBh = g_Whh0h; pBl = g_Whh0l;
            kk = kt * 16;
        } else if (kt < 128) {
            pAh = g_h0h[p ^ 1]; pAl = g_h0l[p ^ 1]; pBh = g_Wih1h; pBl = g_Wih1l;
            kk = kt * 16;
        } else {
            pAh = g_h1h[p]; pAl = g_h1l[p]; pBh = g_Whh1h; pBl = g_Whh1l;
            kk = (kt - 128) * 16;
        }
        const uint32_t sb = sb0 + (uint32_t)buf * STAGE_P;
        const uint32_t so = (uint32_t)(lrow * ROWB_P + lhalf * 16);   // 16-aligned
        const size_t gA = (size_t)(m0 + lrow) * HH + kk + lhalf * 8;
        const size_t gB = (size_t)(n0 + lrow) * HH + kk + lhalf * 8;
        cp16(sb + OFF_A + so,      pAh + gA);
        cp16(sb + OFF_A + so + 32, pAl + gA);
        cp16(sb + OFF_B + so,      pBh + gB);
        cp16(sb + OFF_B + so + 32, pBl + gB);
        asm volatile("cp.async.commit_group;\n" ::: "memory");
    };

    // ldmatrix lane address components (fragment layout validated since R4)
    const int rowA = (lane & 7) + ((lane >> 3) & 1) * 8;
    const int colA = (lane >> 4) * 8;       // halves -> bytes {0,16}: 16-aligned
    const int rowB = (lane & 7) + (lane >> 4) * 8;
    const int colB = ((lane >> 3) & 1) * 8;

    float acc[2][8][4];
#pragma unroll
    for (int i = 0; i < 2; i++)
#pragma unroll
        for (int j = 0; j < 8; j++)
#pragma unroll
            for (int k = 0; k < 4; k++) acc[i][j][k] = 0.0f;

    load_stage(sbeg, 0);
    load_stage(sbeg + 1, 1);

    for (int i = 0; i < nst; i++) {
        const int buf = i & 1;
        if (i < nst - 1) {
            asm volatile("cp.async.wait_group 1;\n" ::: "memory");
        } else {
            asm volatile("cp.async.wait_group 0;\n" ::: "memory");
        }
        __syncthreads();

        const uint32_t base = sb0 + (uint32_t)buf * STAGE_P;
        uint32_t ah[2][4], al[2][4];
#pragma unroll
        for (int mt = 0; mt < 2; mt++) {
            const uint32_t ao = (uint32_t)((wm * 32 + mt * 16 + rowA) * ROWB_P + colA * 2);
            ldsm4(ah[mt], base + OFF_A + ao);
            ldsm4(al[mt], base + OFF_A + ao + 32);
        }
#pragma unroll
        for (int ng = 0; ng < 4; ng++) {
            uint32_t bh[4], bl[4];
            const uint32_t bo = (uint32_t)((wn * 64 + ng * 16 + rowB) * ROWB_P + colB * 2);
            ldsm4(bh, base + OFF_B + bo);
            ldsm4(bl, base + OFF_B + bo + 32);
#pragma unroll
            for (int mt = 0; mt < 2; mt++)
#pragma unroll
                for (int h2 = 0; h2 < 2; h2++) {
                    float* a = acc[mt][ng * 2 + h2];
                    mma16(a, ah[mt], bh + h2 * 2);   // hi*hi
                    mma16(a, al[mt], bh + h2 * 2);   // lo*hi
                    mma16(a, ah[mt], bl + h2 * 2);   // hi*lo
                }
        }

        if (i + 2 < nst) {
            __syncthreads();                 // all warps done with this buffer
            load_stage(sbeg + i + 2, buf);   // refill it
        }
    }

    // Write fp32 partial tile (no atomics; finisher reduces)
    float* P = lay ? g_part1[kc] : g_part0[kc];
#pragma unroll
    for (int mt = 0; mt < 2; mt++) {
#pragma unroll
        for (int hi = 0; hi < 2; hi++) {
            const int r = m0 + wm * 32 + mt * 16 + (lane >> 2) + hi * 8;
#pragma unroll
            for (int ng = 0; ng < 4; ng++)
#pragma unroll
                for (int h2 = 0; h2 < 2; h2++) {
                    const int cc = n0 + wn * 64 + ng * 16 + h2 * 8 + (lane & 3) * 2;
                    float2 v;
                    v.x = acc[mt][ng * 2 + h2][hi * 2 + 0];
                    v.y = acc[mt][ng * 2 + h2][hi * 2 + 1];
                    *(float2*)(P + (size_t)r * HH + cc) = v;
                }
        }
    }
}

// ---------------------------------------------------------------------------
// Finisher: fixed-order sum of split-K partials + epilogue. Deterministic.
// blockIdx.y == 0 -> lay1 (t=c-1), == 1 -> lay0 (t=c).
// ---------------------------------------------------------------------------
__global__ __launch_bounds__(256) void finisher_kernel(
    const int* __restrict__ tokens,
    const float* __restrict__ b_ih,
    const float* __restrict__ b_hh,
    int c)
{
    const int lay = (blockIdx.y == 0) ? 1 : 0;
    if (lay == 1 && c == 0) return;
    if (lay == 0 && c >= TT) return;
    const int t = lay ? (c - 1) : c;
    const int p = t & 1;

    const int gi = (blockIdx.x * 256 + threadIdx.x) * 4;   // over BB*HH
    if (gi >= BB * HH) return;
    const int r = gi / HH;
    const int col = gi % HH;

    float o[4];
    if (lay == 1) {
        float4 v = *(const float4*)(g_part1[0] + gi);
#pragma unroll
        for (int k = 1; k < KS1; k++) {
            const float4 q = *(const float4*)(g_part1[k] + gi);
            v.x += q.x; v.y += q.y; v.z += q.z; v.w += q.w;
        }
        o[0] = v.x; o[1] = v.y; o[2] = v.z; o[3] = v.w;
#pragma unroll
        for (int q = 0; q < 4; q++)
            o[q] += b_ih[HH + col + q] + b_hh[HH + col + q];
    } else {
        float4 v = *(const float4*)(g_part0[0] + gi);
#pragma unroll
        for (int k = 1; k < KS0; k++) {
            const float4 q = *(const float4*)(g_part0[k] + gi);
            v.x += q.x; v.y += q.y; v.z += q.z; v.w += q.w;
        }
        const int tok = tokens[r * TT + t];
        const float4 e = *(const float4*)(g_Eprime + (size_t)tok * HH + col);
        o[0] = v.x + e.x; o[1] = v.y + e.y; o[2] = v.z + e.z; o[3] = v.w + e.w;
    }

    __align__(8) __half hv[4];
    __align__(8) __half lv[4];
#pragma unroll
    for (int q = 0; q < 4; q++) {
        const float tv = my_tanh(o[q]);
        f16_split(tv, hv[q], lv[q]);
    }

    if (lay == 0) {
        *(uint64_t*)(g_h0h[p ^ 1] + gi) = *(const uint64_t*)hv;
        *(uint64_t*)(g_h0l[p ^ 1] + gi) = *(const uint64_t*)lv;
    } else {
        *(uint64_t*)(g_h1h[p ^ 1] + gi) = *(const uint64_t*)hv;
        *(uint64_t*)(g_h1l[p ^ 1] + gi) = *(const uint64_t*)lv;
        const size_t oidx = (size_t)t * BB * HH + gi;
        *(uint64_t*)(g_outsh + oidx) = *(const uint64_t*)hv;
        *(uint64_t*)(g_outsl + oidx) = *(const uint64_t*)lv;
    }
}

// ---------------------------------------------------------------------------
// Legacy mma kernel for EPRIME and LOGITS (off critical path; proven shape).
// BM=BN=64, BK=32, 256 threads, single acc (unscaled lo).
// ---------------------------------------------------------------------------
#define MODE_EPRIME 0
#define MODE_LOGITS 3
#define ROWB_G 80
#define STAGEB 5120

template <int MODE>
__global__ __launch_bounds__(256) void gemm_kernel(
    const float* __restrict__ b_ih,
    const float* __restrict__ b_hh,
    const float* __restrict__ fc_b,
    float* __restrict__ d_out)
{
    __shared__ __align__(16) __half Ash[2][64][40];
    __shared__ __align__(16) __half Asl[2][64][40];
    __shared__ __align__(16) __half Bsh[2][64][40];
    __shared__ __align__(16) __half Bsl[2][64][40];

    const __half *A0h, *A0l, *B0h, *B0l;
    int KT;
    if (MODE == MODE_EPRIME) {
        A0h = g_embh; A0l = g_embl; B0h = g_Wih0h; B0l = g_Wih0l; KT = 64;
    } else {
        A0h = g_outsh; A0l = g_outsl; B0h = g_fcwh; B0l = g_fcwl; KT = 64;
    }

    int m0, n0;
    if (MODE == MODE_LOGITS) { m0 = blockIdx.y * 64; n0 = blockIdx.x * 64; }
    else                     { m0 = blockIdx.x * 64; n0 = blockIdx.y * 64; }

    const int tid = threadIdx.x;
    const int lane = tid & 31;
    const int warp = tid >> 5;
    const int wm = warp & 1;
    const int wn = warp >> 1;

    const uint32_t smAh = smem_u32(&Ash[0][0][0]);
    const uint32_t smAl = smem_u32(&Asl[0][0][0]);
    const uint32_t smBh = smem_u32(&Bsh[0][0][0]);
    const uint32_t smBl = smem_u32(&Bsl[0][0][0]);

    const int rowA = (lane & 7) + ((lane >> 3) & 1) * 8;
    const int colA = (lane >> 4) * 8;
    const int rowB = (lane & 7) + (lane >> 4) * 8;
    const int colB = ((lane >> 3) & 1) * 8;
    const uint32_t aOffH = smAh + (uint32_t)((wm * 32 + rowA) * ROWB_G + colA * 2);
    const uint32_t aOffL = smAl + (uint32_t)((wm * 32 + rowA) * ROWB_G + colA * 2);
    const uint32_t bOffH = smBh + (uint32_t)((wn * 16 + rowB) * ROWB_G + colB * 2);
    const uint32_t bOffL = smBl + (uint32_t)((wn * 16 + rowB) * ROWB_G + colB * 2);

    float accc[2][2][4];
#pragma unroll
    for (int i = 0; i < 2; i++)
#pragma unroll
        for (int j = 0; j < 2; j++)
#pragma unroll
            for (int k = 0; k < 4; k++) accc[i][j][k] = 0.0f;

    const int lrow = tid >> 2;
    const int lc8 = (tid & 3) * 8;
    auto load_tile = [&](int kt, int s) {
        int kk = kt * 32;
        const size_t gA = (size_t)(m0 + lrow) * HH + kk + lc8;
        const size_t gB = (size_t)(n0 + lrow) * HH + kk + lc8;
        const uint32_t so = (uint32_t)(s * STAGEB + lrow * ROWB_G + lc8 * 2);
        cp16(smAh + so, A0h + gA);
        cp16(smAl + so, A0l + gA);
        cp16(smBh + so, B0h + gB);
        cp16(smBl + so, B0l + gB);
        asm volatile("cp.async.commit_group;\n" ::: "memory");
    };

    load_tile(0, 0);

    for (int kt = 0; kt < KT; kt++) {
        const int s = kt & 1;
        asm volatile("cp.async.wait_group 0;\n" ::: "memory");
        __syncthreads();
        if (kt + 1 < KT) load_tile(kt + 1, s ^ 1);

        const uint32_t sb = (uint32_t)(s * STAGEB);
#pragma unroll
        for (int ks = 0; ks < 2; ks++) {
            uint32_t ah[2][4], al[2][4], bh[4], bl[4];
            const uint32_t ko = (uint32_t)(ks * 32);
#pragma unroll
            for (int mt = 0; mt < 2; mt++) {
                ldsm4(ah[mt], aOffH + sb + (uint32_t)(mt * 16 * ROWB_G) + ko);
                ldsm4(al[mt], aOffL + sb + (uint32_t)(mt * 16 * ROWB_G) + ko);
            }
            ldsm4(bh, bOffH + sb + ko);
            ldsm4(bl, bOffL + sb + ko);
#pragma unroll
            for (int mt = 0; mt < 2; mt++)
#pragma unroll
                for (int nt = 0; nt < 2; nt++) {
                    mma16(accc[mt][nt], ah[mt], bh + nt * 2);
                    mma16(accc[mt][nt], al[mt], bh + nt * 2);
                    mma16(accc[mt][nt], ah[mt], bl + nt * 2);
                }
        }
    }

#pragma unroll
    for (int mt = 0; mt < 2; mt++) {
#pragma unroll
        for (int hi = 0; hi < 2; hi++) {
            const int r = m0 + wm * 32 + mt * 16 + (lane >> 2) + hi * 8;
#pragma unroll
            for (int nt = 0; nt < 2; nt++) {
#pragma unroll
                for (int lo = 0; lo < 2; lo++) {
                    const int cc = n0 + wn * 16 + nt * 8 + (lane & 3) * 2 + lo;
                    float v = accc[mt][nt][hi * 2 + lo];
                    if (MODE == MODE_EPRIME) {
                        v += b_ih[cc] + b_hh[cc];
                        g_Eprime[(size_t)r * HH + cc] = v;
                    } else {
                        v += fc_b[cc];
                        d_out[(size_t)r * VV + cc] = v;
                    }
                }
            }
        }
    }
}

// ---------------------------------------------------------------------------
// h_final (last step wrote parity 0; h = hi + lo, unscaled)
// ---------------------------------------------------------------------------
__global__ void final_copy_kernel(float* __restrict__ d_out) {
    int i = blockIdx.x * blockDim.x + threadIdx.x;
    if (i < BB * HH) {
        d_out[(size_t)TT * BB * VV + i] =
            __half2float(g_h0h[0][i]) + __half2float(g_h0l[0][i]);
        d_out[(size_t)TT * BB * VV + BB * HH + i] =
            __half2float(g_h1h[0][i]) + __half2float(g_h1l[0][i]);
    }
}

// ---------------------------------------------------------------------------
// Launch
// ---------------------------------------------------------------------------
extern "C" void kernel_launch(void* const* d_in, const int* in_sizes, int n_in,
                              void* d_out, int out_size) {
    const int*   tokens = (const int*)d_in[0];
    const float* h0     = (const float*)d_in[1];
    const float* emb    = (const float*)d_in[2];
    const float* Wih    = (const float*)d_in[3];
    const float* Whh    = (const float*)d_in[4];
    const float* bih    = (const float*)d_in[5];
    const float* bhh    = (const float*)d_in[6];
    const float* fcw    = (const float*)d_in[7];
    const float* fcb    = (const float*)d_in[8];
    float* out = (float*)d_out;

    // 1) Split weights + initial state into fp16 hi/lo
    prep_kernel<<<1024, 256>>>(h0, emb, Wih, Whh, fcw);

    // 2) E'' = emb @ W_ih0^T + b_ih0 + b_hh0
    gemm_kernel<MODE_EPRIME><<<dim3(VV / 64, HH / 64), 256>>>(bih, bhh, fcb, out);

    // 3) Recurrence: 201 pair launches + finishers.
    //    Launch c: partials for step1(c-1) || step0(c), then reduce+activate.
    for (int c = 0; c <= TT; c++) {
        pair_gemm_kernel<<<dim3(16, 2, KS1 + KS0), 256>>>(c);
        finisher_kernel<<<dim3(BB * HH / 1024, 2), 256>>>(tokens, bih, bhh, c);
    }

    // 4) Logits: [T*B, H] @ [V, H]^T + fc_b
    gemm_kernel<MODE_LOGITS><<<dim3(VV / 64, (TT * BB) / 64), 256>>>(bih, bhh, fcb, out);

    // 5) h_final
    if (out_size >= TT * BB * VV + LL * BB * HH)
        final_copy_kernel<<<(BB * HH + 255) / 256, 256>>>(out);
}

// round 17
// speedup vs baseline: 1.7957x; 1.1156x over previous
#include <cuda_runtime.h>
#include <cuda_fp16.h>
#include <cstdint>
#include <cstddef>

// Problem constants
#define HH 2048
#define BB 256
#define TT 200
#define VV 512
#define LL 2

// ---------------------------------------------------------------------------
// Scratch (static __device__ — no allocations allowed)
// Operands stored as fp16 (hi, lo) pairs, lo UNSCALED (subnormals OK).
// ---------------------------------------------------------------------------
__device__ __align__(128) __half g_Wih0h[HH * HH];
__device__ __align__(128) __half g_Wih0l[HH * HH];
__device__ __align__(128) __half g_Whh0h[HH * HH];
__device__ __align__(128) __half g_Whh0l[HH * HH];
__device__ __align__(128) __half g_Wih1h[HH * HH];
__device__ __align__(128) __half g_Wih1l[HH * HH];
__device__ __align__(128) __half g_Whh1h[HH * HH];
__device__ __align__(128) __half g_Whh1l[HH * HH];
__device__ __align__(128) __half g_embh[VV * HH];
__device__ __align__(128) __half g_embl[VV * HH];
__device__ __align__(128) __half g_fcwh[VV * HH];
__device__ __align__(128) __half g_fcwl[VV * HH];
__device__ __align__(128) float  g_Eprime[VV * HH];
__device__ __align__(128) __half g_h0h[2][BB * HH];
__device__ __align__(128) __half g_h0l[2][BB * HH];
__device__ __align__(128) __half g_h1h[2][BB * HH];
__device__ __align__(128) __half g_h1l[2][BB * HH];
__device__ __align__(128) __half g_outsh[(size_t)TT * BB * HH];
__device__ __align__(128) __half g_outsl[(size_t)TT * BB * HH];

// Split-K partial accumulators (fp32); reduced by a separate finisher kernel.
// 6 + 3 chunks -> grid 16*2*9 = 288 CTAs = exactly one wave at occ 2.
#define KS1 6
#define KS0 3
__device__ __align__(128) float g_part1[KS1][BB * HH];
__device__ __align__(128) float g_part0[KS0][BB * HH];

// Stage counts (BK=16): lay1 K=4096 -> 256 stages; lay0 K=2048 -> 128 stages.
#define S1 256
#define S0 128

// ---------------------------------------------------------------------------
// Helpers
// ---------------------------------------------------------------------------
__device__ __forceinline__ void f16_split(float x, __half& hi, __half& lo) {
    __half h = __float2half_rn(x);
    hi = h;
    lo = __float2half_rn(x - __half2float(h));   // unscaled residual
}

// tanh immune to --use_fast_math's tanh.approx (too inaccurate).
__device__ __forceinline__ float my_tanh(float x) {
    float e = __expf(2.0f * x);
    return 1.0f - 2.0f / (e + 1.0f);
}

__device__ __forceinline__ void cp16(uint32_t smem_addr, const void* src) {
    asm volatile("cp.async.cg.shared.global [%0], [%1], 16;\n"
                 :: "r"(smem_addr), "l"(src));
}

__device__ __forceinline__ void ldsm4(uint32_t* r, uint32_t addr) {
    asm volatile("ldmatrix.sync.aligned.m8n8.x4.shared.b16 {%0,%1,%2,%3}, [%4];\n"
                 : "=r"(r[0]), "=r"(r[1]), "=r"(r[2]), "=r"(r[3])
                 : "r"(addr));
}

__device__ __forceinline__ void mma16(float* c, const uint32_t* a, const uint32_t* b) {
    asm volatile(
        "mma.sync.aligned.m16n8k16.row.col.f32.f16.f16.f32 "
        "{%0,%1,%2,%3}, {%4,%5,%6,%7}, {%8,%9}, {%0,%1,%2,%3};\n"
        : "+f"(c[0]), "+f"(c[1]), "+f"(c[2]), "+f"(c[3])
        : "r"(a[0]), "r"(a[1]), "r"(a[2]), "r"(a[3]),
          "r"(b[0]), "r"(b[1]));
}

__device__ __forceinline__ uint32_t smem_u32(const void* p) {
    return (uint32_t)__cvta_generic_to_shared(p);
}

// ---------------------------------------------------------------------------
// Prep: split all weights + initial hidden state into fp16 hi/lo
// ---------------------------------------------------------------------------
__global__ void prep_kernel(const float* __restrict__ h0,
                            const float* __restrict__ emb,
                            const float* __restrict__ Wih,
                            const float* __restrict__ Whh,
                            const float* __restrict__ fcw) {
    int idx = blockIdx.x * blockDim.x + threadIdx.x;
    int stride = gridDim.x * blockDim.x;
    for (int i = idx; i < HH * HH; i += stride) {
        f16_split(Wih[i],           g_Wih0h[i], g_Wih0l[i]);
        f16_split(Wih[HH * HH + i], g_Wih1h[i], g_Wih1l[i]);
        f16_split(Whh[i],           g_Whh0h[i], g_Whh0l[i]);
        f16_split(Whh[HH * HH + i], g_Whh1h[i], g_Whh1l[i]);
    }
    for (int i = idx; i < VV * HH; i += stride) {
        f16_split(emb[i], g_embh[i], g_embl[i]);
        f16_split(fcw[i], g_fcwh[i], g_fcwl[i]);
    }
    for (int i = idx; i < BB * HH; i += stride) {
        f16_split(h0[i],           g_h0h[0][i], g_h0l[0][i]);
        f16_split(h0[BB * HH + i], g_h1h[0][i], g_h1l[0][i]);
    }
}

// ---------------------------------------------------------------------------
// Pair GEMM with split-K (partials only; reduction in finisher_kernel).
// Launch c computes:
//   lay=1 (z 0..5): step1(c-1) partials: h0'@Wih1^T + h1@Whh1^T, K=4096
//   lay=0 (z 6..8): step0(c)   partials: h0 @Whh0^T,             K=2048
// CTA tile BM=128, BN=128, BK=16, 3-stage STATIC smem (48 KB exactly),
// 256 threads = 8 warps (4M x 2N), warp region 32x64, single fp32 acc,
// 3 mma passes. ONE __syncthreads per stage (refill targets the buffer
// consumed last stage, protected by this stage's barrier).
// Smem row 64 B = 4x16B chunks [hi0|hi1|lo0|lo1], XOR-swizzled:
//   phys_chunk = chunk ^ ((row>>1)&3)  -> conflict-free ldmatrix, 16B-aligned.
// ---------------------------------------------------------------------------
#define ROWB_P 64                 // bytes per smem row
#define ARR_P  (128 * ROWB_P)     // 8192 B per operand (A or B)
#define STAGE_P (2 * ARR_P)       // 16384 B per stage
#define OFF_A 0
#define OFF_B ARR_P
#define NST_P 3                   // pipeline stages (3*16384 = 49152 = 48KB)

__global__ __launch_bounds__(256, 2) void pair_gemm_kernel(int c)
{
    __shared__ __align__(128) char sm[NST_P * STAGE_P];   // 49152 B, static

    const int tid = threadIdx.x;
    const int lane = tid & 31;
    const int warp = tid >> 5;
    const int wm = warp & 3;    // 4 warps over M (32 rows each)
    const int wn = warp >> 2;   // 2 warps over N (64 cols each)
    const int n0 = blockIdx.x * 128;
    const int m0 = blockIdx.y * 128;

    int lay, kc, t, sbeg, send;
    if (blockIdx.z < KS1) {
        if (c == 0) return;
        lay = 1; kc = (int)blockIdx.z; t = c - 1;
        sbeg = (S1 * kc) / KS1; send = (S1 * (kc + 1)) / KS1;
    } else {
        if (c >= TT) return;
        lay = 0; kc = (int)blockIdx.z - KS1; t = c;
        sbeg = (S0 * kc) / KS0; send = (S0 * (kc + 1)) / KS0;
    }
    const int p = t & 1;
    const int nst = send - sbeg;

    const uint32_t sb0 = smem_u32(sm);

    // Stage loader: 256 threads, 4 cp.async(16B) each.
    // Thread -> (row = tid>>1, half = tid&1).
    // Logical chunks: hi -> half, lo -> 2+half; physical = chunk ^ ((row>>1)&3).
    const int lrow = tid >> 1;            // 0..127
    const int lhalf = tid & 1;            // which 8-half chunk
    const int lsw = (lrow >> 1) & 3;
    const uint32_t soHi = (uint32_t)(lrow * ROWB_P + (lhalf ^ lsw) * 16);
    const uint32_t soLo = (uint32_t)(lrow * ROWB_P + ((2 + lhalf) ^ lsw) * 16);
    auto load_stage = [&](int kt, int buf) {
        const __half *pAh, *pAl, *pBh, *pBl;
        int kk;
        if (lay == 0) {
            pAh = g_h0h[p]; pAl = g_h0l[p]; pBh = g_Whh0h; pBl = g_Whh0l;
            kk = kt * 16;
        } else if (kt < 128) {
            pAh = g_h0h[p ^ 1]; pAl = g_h0l[p ^ 1]; pBh = g_Wih1h; pBl = g_Wih1l;
            kk = kt * 16;
        } else {
            pAh = g_h1h[p]; pAl = g_h1l[p]; pBh = g_Whh1h; pBl = g_Whh1l;
            kk = (kt - 128) * 16;
        }
        const uint32_t sb = sb0 + (uint32_t)buf * STAGE_P;
        const size_t gA = (size_t)(m0 + lrow) * HH + kk + lhalf * 8;
        const size_t gB = (size_t)(n0 + lrow) * HH + kk + lhalf * 8;
        cp16(sb + OFF_A + soHi, pAh + gA);
        cp16(sb + OFF_A + soLo, pAl + gA);
        cp16(sb + OFF_B + soHi, pBh + gB);
        cp16(sb + OFF_B + soLo, pBl + gB);
        asm volatile("cp.async.commit_group;\n" ::: "memory");
    };

    // ldmatrix lane address components. Each 8-lane phase = 8 consecutive
    // rows, fixed logical chunk; the XOR swizzle makes the 8 addresses hit
    // 8 distinct bank groups. lo address = hi address XOR 32.
    const int rowA = (lane & 7) + ((lane >> 3) & 1) * 8;
    const int chA  = lane >> 4;             // logical chunk 0/1 (k halves)
    const int rowB = (lane & 7) + (lane >> 4) * 8;
    const int chB  = (lane >> 3) & 1;

    float acc[2][8][4];
#pragma unroll
    for (int i = 0; i < 2; i++)
#pragma unroll
        for (int j = 0; j < 8; j++)
#pragma unroll
            for (int k = 0; k < 4; k++) acc[i][j][k] = 0.0f;

    load_stage(sbeg, 0);
    load_stage(sbeg + 1, 1);

    for (int i = 0; i < nst; i++) {
        const int buf = i % NST_P;
        if (i < nst - 1) {
            asm volatile("cp.async.wait_group 1;\n" ::: "memory");
        } else {
            asm volatile("cp.async.wait_group 0;\n" ::: "memory");
        }
        __syncthreads();   // stage i ready; also frees buffer consumed at i-1

        // Prefetch stage i+2 into the buffer consumed at stage i-1.
        if (i + 2 < nst) load_stage(sbeg + i + 2, (i + 2) % NST_P);

        const uint32_t base = sb0 + (uint32_t)buf * STAGE_P;
        uint32_t ah[2][4], al[2][4];
#pragma unroll
        for (int mt = 0; mt < 2; mt++) {
            const int rA = wm * 32 + mt * 16 + rowA;
            const uint32_t ao = (uint32_t)(rA * ROWB_P + ((chA ^ ((rA >> 1) & 3)) * 16));
            ldsm4(ah[mt], base + OFF_A + ao);
            ldsm4(al[mt], base + OFF_A + (ao ^ 32u));
        }
#pragma unroll
        for (int ng = 0; ng < 4; ng++) {
            uint32_t bh[4], bl[4];
            const int rB = wn * 64 + ng * 16 + rowB;
            const uint32_t bo = (uint32_t)(rB * ROWB_P + ((chB ^ ((rB >> 1) & 3)) * 16));
            ldsm4(bh, base + OFF_B + bo);
            ldsm4(bl, base + OFF_B + (bo ^ 32u));
#pragma unroll
            for (int mt = 0; mt < 2; mt++)
#pragma unroll
                for (int h2 = 0; h2 < 2; h2++) {
                    float* a = acc[mt][ng * 2 + h2];
                    mma16(a, ah[mt], bh + h2 * 2);   // hi*hi
                    mma16(a, al[mt], bh + h2 * 2);   // lo*hi
                    mma16(a, ah[mt], bl + h2 * 2);   // hi*lo
                }
        }
    }

    // Write fp32 partial tile (no atomics; finisher reduces)
    float* P = lay ? g_part1[kc] : g_part0[kc];
#pragma unroll
    for (int mt = 0; mt < 2; mt++) {
#pragma unroll
        for (int hi = 0; hi < 2; hi++) {
            const int r = m0 + wm * 32 + mt * 16 + (lane >> 2) + hi * 8;
#pragma unroll
            for (int ng = 0; ng < 4; ng++)
#pragma unroll
                for (int h2 = 0; h2 < 2; h2++) {
                    const int cc = n0 + wn * 64 + ng * 16 + h2 * 8 + (lane & 3) * 2;
                    float2 v;
                    v.x = acc[mt][ng * 2 + h2][hi * 2 + 0];
                    v.y = acc[mt][ng * 2 + h2][hi * 2 + 1];
                    *(float2*)(P + (size_t)r * HH + cc) = v;
                }
        }
    }
}

// ---------------------------------------------------------------------------
// Finisher: fixed-order sum of split-K partials + epilogue. Deterministic.
// blockIdx.y == 0 -> lay1 (t=c-1), == 1 -> lay0 (t=c).
// ---------------------------------------------------------------------------
__global__ __launch_bounds__(256) void finisher_kernel(
    const int* __restrict__ tokens,
    const float* __restrict__ b_ih,
    const float* __restrict__ b_hh,
    int c)
{
    const int lay = (blockIdx.y == 0) ? 1 : 0;
    if (lay == 1 && c == 0) return;
    if (lay == 0 && c >= TT) return;
    const int t = lay ? (c - 1) : c;
    const int p = t & 1;

    const int gi = (blockIdx.x * 256 + threadIdx.x) * 4;   // over BB*HH
    if (gi >= BB * HH) return;
    const int r = gi / HH;
    const int col = gi % HH;

    float o[4];
    if (lay == 1) {
        float4 v = *(const float4*)(g_part1[0] + gi);
#pragma unroll
        for (int k = 1; k < KS1; k++) {
            const float4 q = *(const float4*)(g_part1[k] + gi);
            v.x += q.x; v.y += q.y; v.z += q.z; v.w += q.w;
        }
        o[0] = v.x; o[1] = v.y; o[2] = v.z; o[3] = v.w;
#pragma unroll
        for (int q = 0; q < 4; q++)
            o[q] += b_ih[HH + col + q] + b_hh[HH + col + q];
    } else {
        float4 v = *(const float4*)(g_part0[0] + gi);
#pragma unroll
        for (int k = 1; k < KS0; k++) {
            const float4 q = *(const float4*)(g_part0[k] + gi);
            v.x += q.x; v.y += q.y; v.z += q.z; v.w += q.w;
        }
        const int tok = tokens[r * TT + t];
        const float4 e = *(const float4*)(g_Eprime + (size_t)tok * HH + col);
        o[0] = v.x + e.x; o[1] = v.y + e.y; o[2] = v.z + e.z; o[3] = v.w + e.w;
    }

    __align__(8) __half hv[4];
    __align__(8) __half lv[4];
#pragma unroll
    for (int q = 0; q < 4; q++) {
        const float tv = my_tanh(o[q]);
        f16_split(tv, hv[q], lv[q]);
    }

    if (lay == 0) {
        *(uint64_t*)(g_h0h[p ^ 1] + gi) = *(const uint64_t*)hv;
        *(uint64_t*)(g_h0l[p ^ 1] + gi) = *(const uint64_t*)lv;
    } else {
        *(uint64_t*)(g_h1h[p ^ 1] + gi) = *(const uint64_t*)hv;
        *(uint64_t*)(g_h1l[p ^ 1] + gi) = *(const uint64_t*)lv;
        const size_t oidx = (size_t)t * BB * HH + gi;
        *(uint64_t*)(g_outsh + oidx) = *(const uint64_t*)hv;
        *(uint64_t*)(g_outsl + oidx) = *(const uint64_t*)lv;
    }
}

// ---------------------------------------------------------------------------
// Legacy mma kernel for EPRIME and LOGITS (off critical path; proven shape).
// BM=BN=64, BK=32, 256 threads, single acc (unscaled lo).
// ---------------------------------------------------------------------------
#define MODE_EPRIME 0
#define MODE_LOGITS 3
#define ROWB_G 80
#define STAGEB 5120

template <int MODE>
__global__ __launch_bounds__(256) void gemm_kernel(
    const float* __restrict__ b_ih,
    const float* __restrict__ b_hh,
    const float* __restrict__ fc_b,
    float* __restrict__ d_out)
{
    __shared__ __align__(16) __half Ash[2][64][40];
    __shared__ __align__(16) __half Asl[2][64][40];
    __shared__ __align__(16) __half Bsh[2][64][40];
    __shared__ __align__(16) __half Bsl[2][64][40];

    const __half *A0h, *A0l, *B0h, *B0l;
    int KT;
    if (MODE == MODE_EPRIME) {
        A0h = g_embh; A0l = g_embl; B0h = g_Wih0h; B0l = g_Wih0l; KT = 64;
    } else {
        A0h = g_outsh; A0l = g_outsl; B0h = g_fcwh; B0l = g_fcwl; KT = 64;
    }

    int m0, n0;
    if (MODE == MODE_LOGITS) { m0 = blockIdx.y * 64; n0 = blockIdx.x * 64; }
    else                     { m0 = blockIdx.x * 64; n0 = blockIdx.y * 64; }

    const int tid = threadIdx.x;
    const int lane = tid & 31;
    const int warp = tid >> 5;
    const int wm = warp & 1;
    const int wn = warp >> 1;

    const uint32_t smAh = smem_u32(&Ash[0][0][0]);
    const uint32_t smAl = smem_u32(&Asl[0][0][0]);
    const uint32_t smBh = smem_u32(&Bsh[0][0][0]);
    const uint32_t smBl = smem_u32(&Bsl[0][0][0]);

    const int rowA = (lane & 7) + ((lane >> 3) & 1) * 8;
    const int colA = (lane >> 4) * 8;
    const int rowB = (lane & 7) + (lane >> 4) * 8;
    const int colB = ((lane >> 3) & 1) * 8;
    const uint32_t aOffH = smAh + (uint32_t)((wm * 32 + rowA) * ROWB_G + colA * 2);
    const uint32_t aOffL = smAl + (uint32_t)((wm * 32 + rowA) * ROWB_G + colA * 2);
    const uint32_t bOffH = smBh + (uint32_t)((wn * 16 + rowB) * ROWB_G + colB * 2);
    const uint32_t bOffL = smBl + (uint32_t)((wn * 16 + rowB) * ROWB_G + colB * 2);

    float accc[2][2][4];
#pragma unroll
    for (int i = 0; i < 2; i++)
#pragma unroll
        for (int j = 0; j < 2; j++)
#pragma unroll
            for (int k = 0; k < 4; k++) accc[i][j][k] = 0.0f;

    const int lrow = tid >> 2;
    const int lc8 = (tid & 3) * 8;
    auto load_tile = [&](int kt, int s) {
        int kk = kt * 32;
        const size_t gA = (size_t)(m0 + lrow) * HH + kk + lc8;
        const size_t gB = (size_t)(n0 + lrow) * HH + kk + lc8;
        const uint32_t so = (uint32_t)(s * STAGEB + lrow * ROWB_G + lc8 * 2);
        cp16(smAh + so, A0h + gA);
        cp16(smAl + so, A0l + gA);
        cp16(smBh + so, B0h + gB);
        cp16(smBl + so, B0l + gB);
        asm volatile("cp.async.commit_group;\n" ::: "memory");
    };

    load_tile(0, 0);

    for (int kt = 0; kt < KT; kt++) {
        const int s = kt & 1;
        asm volatile("cp.async.wait_group 0;\n" ::: "memory");
        __syncthreads();
        if (kt + 1 < KT) load_tile(kt + 1, s ^ 1);

        const uint32_t sb = (uint32_t)(s * STAGEB);
#pragma unroll
        for (int ks = 0; ks < 2; ks++) {
            uint32_t ah[2][4], al[2][4], bh[4], bl[4];
            const uint32_t ko = (uint32_t)(ks * 32);
#pragma unroll
            for (int mt = 0; mt < 2; mt++) {
                ldsm4(ah[mt], aOffH + sb + (uint32_t)(mt * 16 * ROWB_G) + ko);
                ldsm4(al[mt], aOffL + sb + (uint32_t)(mt * 16 * ROWB_G) + ko);
            }
            ldsm4(bh, bOffH + sb + ko);
            ldsm4(bl, bOffL + sb + ko);
#pragma unroll
            for (int mt = 0; mt < 2; mt++)
#pragma unroll
                for (int nt = 0; nt < 2; nt++) {
                    mma16(accc[mt][nt], ah[mt], bh + nt * 2);
                    mma16(accc[mt][nt], al[mt], bh + nt * 2);
                    mma16(accc[mt][nt], ah[mt], bl + nt * 2);
                }
        }
    }

#pragma unroll
    for (int mt = 0; mt < 2; mt++) {
#pragma unroll
        for (int hi = 0; hi < 2; hi++) {
            const int r = m0 + wm * 32 + mt * 16 + (lane >> 2) + hi * 8;
#pragma unroll
            for (int nt = 0; nt < 2; nt++) {
#pragma unroll
                for (int lo = 0; lo < 2; lo++) {
                    const int cc = n0 + wn * 16 + nt * 8 + (lane & 3) * 2 + lo;
                    float v = accc[mt][nt][hi * 2 + lo];
                    if (MODE == MODE_EPRIME) {
                        v += b_ih[cc] + b_hh[cc];
                        g_Eprime[(size_t)r * HH + cc] = v;
                    } else {
                        v += fc_b[cc];
                        d_out[(size_t)r * VV + cc] = v;
                    }
                }
            }
        }
    }
}

// ---------------------------------------------------------------------------
// h_final (last step wrote parity 0; h = hi + lo, unscaled)
// ---------------------------------------------------------------------------
__global__ void final_copy_kernel(float* __restrict__ d_out) {
    int i = blockIdx.x * blockDim.x + threadIdx.x;
    if (i < BB * HH) {
        d_out[(size_t)TT * BB * VV + i] =
            __half2float(g_h0h[0][i]) + __half2float(g_h0l[0][i]);
        d_out[(size_t)TT * BB * VV + BB * HH + i] =
            __half2float(g_h1h[0][i]) + __half2float(g_h1l[0][i]);
    }
}

// ---------------------------------------------------------------------------
// Launch
// ---------------------------------------------------------------------------
extern "C" void kernel_launch(void* const* d_in, const int* in_sizes, int n_in,
                              void* d_out, int out_size) {
    const int*   tokens = (const int*)d_in[0];
    const float* h0     = (const float*)d_in[1];
    const float* emb    = (const float*)d_in[2];
    const float* Wih    = (const float*)d_in[3];
    const float* Whh    = (const float*)d_in[4];
    const float* bih    = (const float*)d_in[5];
    const float* bhh    = (const float*)d_in[6];
    const float* fcw    = (const float*)d_in[7];
    const float* fcb    = (const float*)d_in[8];
    float* out = (float*)d_out;

    // 1) Split weights + initial state into fp16 hi/lo
    prep_kernel<<<1024, 256>>>(h0, emb, Wih, Whh, fcw);

    // 2) E'' = emb @ W_ih0^T + b_ih0 + b_hh0
    gemm_kernel<MODE_EPRIME><<<dim3(VV / 64, HH / 64), 256>>>(bih, bhh, fcb, out);

    // 3) Recurrence: 201 pair launches + finishers.
    //    Launch c: partials for step1(c-1) || step0(c), then reduce+activate.
    for (int c = 0; c <= TT; c++) {
        pair_gemm_kernel<<<dim3(16, 2, KS1 + KS0), 256>>>(c);
        finisher_kernel<<<dim3(BB * HH / 1024, 2), 256>>>(tokens, bih, bhh, c);
    }

    // 4) Logits: [T*B, H] @ [V, H]^T + fc_b
    gemm_kernel<MODE_LOGITS><<<dim3(VV / 64, (TT * BB) / 64), 256>>>(bih, bhh, fcb, out);

    // 5) h_final
    if (out_size >= TT * BB * VV + LL * BB * HH)
        final_copy_kernel<<<(BB * HH + 255) / 256, 256>>>(out);
}